// round 9
// baseline (speedup 1.0000x reference)
#include <cuda_runtime.h>
#include <math.h>
#include <stdint.h>

#define Bc 16
#define Lc 2048
#define Dc 192
#define Hc 4
#define Kc 12

// ---------------- scratch (no allocations allowed) ----------------
__device__ float g_xn [(size_t)Bc*Lc*Dc];       // xn2 (written by fused proj+LN2)
__device__ float g_q  [(size_t)Bc*Hc*Lc*Kc];    // [B,H,L,K]
__device__ float g_k  [(size_t)Bc*Hc*Lc*Kc];
__device__ float g_v  [(size_t)Bc*Hc*Lc*Kc];
__device__ float g_ctx[(size_t)Bc*Lc*Hc*Kc];    // [B,L,H,K]
__device__ float g_y1 [(size_t)Bc*Lc*Dc];       // x + MHA
__device__ float g_h  [(size_t)Bc*Lc*Dc];       // relu(conv1), zero rows 0, L-1

__device__ __forceinline__ float ex2(float x) {
    float y; asm("ex2.approx.f32 %0, %1;" : "=f"(y) : "f"(x)); return y;
}
__device__ __forceinline__ float to_tf32(float x) {
    uint32_t u; asm("cvt.rna.tf32.f32 %0, %1;" : "=r"(u) : "f"(x));
    return __uint_as_float(u);
}
__device__ __forceinline__ void mma_tf32(float* c, const uint32_t* a,
                                         uint32_t b0, uint32_t b1)
{
    asm volatile(
        "mma.sync.aligned.m16n8k8.row.col.f32.tf32.tf32.f32 "
        "{%0,%1,%2,%3}, {%4,%5,%6,%7}, {%8,%9}, {%0,%1,%2,%3};"
        : "+f"(c[0]), "+f"(c[1]), "+f"(c[2]), "+f"(c[3])
        : "r"(a[0]), "r"(a[1]), "r"(a[2]), "r"(a[3]), "r"(b0), "r"(b1));
}
__device__ __forceinline__ void cp16(uint32_t dst_smem, const void* src) {
    asm volatile("cp.async.ca.shared.global [%0], [%1], 16;"
                 :: "r"(dst_smem), "l"(src));
}
__device__ __forceinline__ void cp_commit() {
    asm volatile("cp.async.commit_group;" ::: "memory");
}
__device__ __forceinline__ void cp_wait0() {
    asm volatile("cp.async.wait_group 0;" ::: "memory");
}

// ---------------- QKV projection + fused LN1: tf32 MMA ----------------
// M=64/block, N=3x48, K=192. 192 threads = 6 warps.
#define QA_S 196
#define QB_S 152
#define QA_FLOATS (64 * QA_S)
#define QB_FLOATS (32 * QB_S)
#define QKV_SMEM_BYTES ((QA_FLOATS + 2 * QB_FLOATS) * 4)

__global__ __launch_bounds__(192, 2)
void qkv_mma_kernel(const float* __restrict__ x,
                    const float* __restrict__ ln_g, const float* __restrict__ ln_b,
                    const float* __restrict__ wq, const float* __restrict__ bq,
                    const float* __restrict__ wk, const float* __restrict__ bk,
                    const float* __restrict__ wv, const float* __restrict__ bv)
{
    extern __shared__ float smem[];
    float* sA = smem;                 // [64][196] raw x rows -> LN'd tf32 in-place
    float* sB = smem + QA_FLOATS;     // [2][32][152] tf32 weights (q|k|v cols)

    const int tid  = threadIdx.x;
    const int w    = tid >> 5;
    const int lane = tid & 31;
    const int tig  = lane & 3;
    const int grp  = lane >> 2;
    const int rowbase = blockIdx.x * 64;
    const int bb   = rowbase / Lc;
    const int lloc = rowbase % Lc;

    auto loadW = [&](int kc, int bf) {
        float* dstb = sB + bf * QB_FLOATS;
#pragma unroll
        for (int it = 0; it < 6; it++) {
            int idx = tid + it * 192;            // 32*36 float4 = 1152
            int k = idx / 36, c = (idx % 36) * 4;
            int m = c / 48, lc = c % 48;
            const float* src = (m == 0) ? wq : (m == 1) ? wk : wv;
            float4 v = *(const float4*)(src + (size_t)(kc * 32 + k) * 48 + lc);
            float* d = dstb + k * QB_S + c;
            d[0] = to_tf32(v.x); d[1] = to_tf32(v.y);
            d[2] = to_tf32(v.z); d[3] = to_tf32(v.w);
        }
    };

    for (int idx = tid; idx < 64 * 48; idx += 192) {
        int r = idx / 48, c4 = (idx % 48) * 4;
        *(float4*)(sA + r * QA_S + c4) =
            *(const float4*)(x + (size_t)(rowbase + r) * Dc + c4);
    }
    loadW(0, 0);
    __syncthreads();

    // fused LN1: warp w handles rows w, w+6, ...
    for (int r = w; r < 64; r += 6) {
        float vv[6]; float s = 0.f;
#pragma unroll
        for (int i = 0; i < 6; i++) { vv[i] = sA[r * QA_S + lane + 32*i]; s += vv[i]; }
#pragma unroll
        for (int o = 16; o; o >>= 1) s += __shfl_xor_sync(0xffffffffu, s, o);
        float mean = s * (1.f/192.f);
        float vs = 0.f;
#pragma unroll
        for (int i = 0; i < 6; i++) { float dd = vv[i] - mean; vs += dd*dd; }
#pragma unroll
        for (int o = 16; o; o >>= 1) vs += __shfl_xor_sync(0xffffffffu, vs, o);
        float inv = rsqrtf(vs * (1.f/192.f) + 1e-3f);
#pragma unroll
        for (int i = 0; i < 6; i++) {
            int c = lane + 32*i;
            sA[r * QA_S + c] = to_tf32((vv[i] - mean) * inv * ln_g[c] + ln_b[c]);
        }
    }
    __syncthreads();

    const int s     = w >> 1;
    const int mbase = (w & 1) * 32;
    float c[2][6][4];
#pragma unroll
    for (int i = 0; i < 2; i++)
#pragma unroll
        for (int j = 0; j < 6; j++)
#pragma unroll
            for (int q = 0; q < 4; q++) c[i][j][q] = 0.f;

    int buf = 0;
    for (int kc = 0; kc < 6; kc++) {
        if (kc < 5) loadW(kc + 1, buf ^ 1);
        const float* bBuf = sB + buf * QB_FLOATS + s * 48;
#pragma unroll
        for (int ks = 0; ks < 4; ks++) {
            const int c0 = kc * 32 + ks * 8;
            uint32_t a[2][4];
#pragma unroll
            for (int mt = 0; mt < 2; mt++) {
                const float* ap = sA + (mbase + mt * 16 + grp) * QA_S + c0 + tig;
                a[mt][0] = __float_as_uint(ap[0]);
                a[mt][1] = __float_as_uint(ap[8 * QA_S]);
                a[mt][2] = __float_as_uint(ap[4]);
                a[mt][3] = __float_as_uint(ap[8 * QA_S + 4]);
            }
            const float* bp = bBuf + (ks * 8 + tig) * QB_S + grp;
#pragma unroll
            for (int nt = 0; nt < 6; nt++) {
                uint32_t b0 = __float_as_uint(bp[nt * 8]);
                uint32_t b1 = __float_as_uint(bp[nt * 8 + 4 * QB_S]);
                mma_tf32(c[0][nt], a[0], b0, b1);
                mma_tf32(c[1][nt], a[1], b0, b1);
            }
        }
        __syncthreads();
        buf ^= 1;
    }

    const float* Bp = (s == 0) ? bq : (s == 1) ? bk : bv;
    float* O = (s == 0) ? g_q : (s == 1) ? g_k : g_v;
#pragma unroll
    for (int mt = 0; mt < 2; mt++) {
#pragma unroll
        for (int rs = 0; rs < 2; rs++) {
            int l = lloc + mbase + mt * 16 + grp + rs * 8;
#pragma unroll
            for (int nt = 0; nt < 6; nt++) {
                int n = nt * 8 + tig * 2;       // 0..47, even
                int h = n / 12, kk = n % 12;
                float2 res;
                res.x = c[mt][nt][rs * 2 + 0] + Bp[n];
                res.y = c[mt][nt][rs * 2 + 1] + Bp[n + 1];
                *(float2*)(O + (((size_t)bb * Hc + h) * Lc + l) * Kc + kk) = res;
            }
        }
    }
}

// ---------------- causal attention: 2 queries/thread, cp.async double-buffer ---
// block 128 threads -> 256 queries; l1 = 256*qt + t, l2 = l1 + 128.
// MODE 0: both full. MODE 1: q1 masked (mm<=t), q2 full. MODE 2: q1 skip, q2 masked.
template<int MODE>
__device__ __forceinline__ void attn_tile2(const float4* __restrict__ sk,
                                           const float4* __restrict__ sv,
                                           int t,
                                           const float* q1, const float* q2,
                                           float* o1, float* o2,
                                           float& d1, float& d2)
{
#pragma unroll 4
    for (int mm = 0; mm < 128; mm++) {
        float4 ka = sk[3*mm], kb = sk[3*mm+1], kc = sk[3*mm+2];
        float p1 = 0.f;
        if (MODE < 2) {
            float s1 = q1[0]*ka.x + q1[1]*ka.y + q1[2]*ka.z + q1[3]*ka.w
                     + q1[4]*kb.x + q1[5]*kb.y + q1[6]*kb.z + q1[7]*kb.w
                     + q1[8]*kc.x + q1[9]*kc.y + q1[10]*kc.z + q1[11]*kc.w;
            p1 = ex2(s1);
            if (MODE == 1 && mm > t) p1 = 0.f;
        }
        float s2 = q2[0]*ka.x + q2[1]*ka.y + q2[2]*ka.z + q2[3]*ka.w
                 + q2[4]*kb.x + q2[5]*kb.y + q2[6]*kb.z + q2[7]*kb.w
                 + q2[8]*kc.x + q2[9]*kc.y + q2[10]*kc.z + q2[11]*kc.w;
        float p2 = ex2(s2);
        if (MODE == 2 && mm > t) p2 = 0.f;
        d1 += p1; d2 += p2;
        float4 va = sv[3*mm], vb = sv[3*mm+1], vc = sv[3*mm+2];
        if (MODE < 2) {
            o1[0] += p1*va.x; o1[1] += p1*va.y; o1[2]  += p1*va.z; o1[3]  += p1*va.w;
            o1[4] += p1*vb.x; o1[5] += p1*vb.y; o1[6]  += p1*vb.z; o1[7]  += p1*vb.w;
            o1[8] += p1*vc.x; o1[9] += p1*vc.y; o1[10] += p1*vc.z; o1[11] += p1*vc.w;
        }
        o2[0] += p2*va.x; o2[1] += p2*va.y; o2[2]  += p2*va.z; o2[3]  += p2*va.w;
        o2[4] += p2*vb.x; o2[5] += p2*vb.y; o2[6]  += p2*vb.z; o2[7]  += p2*vb.w;
        o2[8] += p2*vc.x; o2[9] += p2*vc.y; o2[10] += p2*vc.z; o2[11] += p2*vc.w;
    }
}

__global__ __launch_bounds__(128)
void attn_kernel()
{
    __shared__ float4 s_k[2][384];   // [buf][128 keys * 3 float4]
    __shared__ float4 s_v[2][384];
    int qt = gridDim.x - 1 - blockIdx.x;    // heavy tiles first
    int h = blockIdx.y, bb = blockIdx.z;
    int t = threadIdx.x;
    int l1 = qt * 256 + t;
    int l2 = l1 + 128;

    size_t head = ((size_t)bb * Hc + h) * Lc * Kc;
    const float4* qb = (const float4*)(g_q + head);
    const float4* kb4 = (const float4*)(g_k + head);
    const float4* vb4 = (const float4*)(g_v + head);

    uint32_t sk_base = (uint32_t)__cvta_generic_to_shared(&s_k[0][0]);
    uint32_t sv_base = (uint32_t)__cvta_generic_to_shared(&s_v[0][0]);

    auto prefetch = [&](int kt, int bf) {
        const float4* ks = kb4 + (size_t)kt * 384;
        const float4* vs = vb4 + (size_t)kt * 384;
        uint32_t kd = sk_base + (uint32_t)bf * 384 * 16;
        uint32_t vd = sv_base + (uint32_t)bf * 384 * 16;
#pragma unroll
        for (int j = 0; j < 3; j++) {
            int idx = t + j * 128;
            cp16(kd + idx * 16, ks + idx);
            cp16(vd + idx * 16, vs + idx);
        }
        cp_commit();
    };

    const float scale = 0.4164682333693345f;   // log2(e)/sqrt(12)
    float q1[12], q2[12];
    {
        float4 a = qb[3*l1], b = qb[3*l1+1], c = qb[3*l1+2];
        q1[0]=a.x*scale; q1[1]=a.y*scale; q1[2]=a.z*scale; q1[3]=a.w*scale;
        q1[4]=b.x*scale; q1[5]=b.y*scale; q1[6]=b.z*scale; q1[7]=b.w*scale;
        q1[8]=c.x*scale; q1[9]=c.y*scale; q1[10]=c.z*scale; q1[11]=c.w*scale;
        a = qb[3*l2]; b = qb[3*l2+1]; c = qb[3*l2+2];
        q2[0]=a.x*scale; q2[1]=a.y*scale; q2[2]=a.z*scale; q2[3]=a.w*scale;
        q2[4]=b.x*scale; q2[5]=b.y*scale; q2[6]=b.z*scale; q2[7]=b.w*scale;
        q2[8]=c.x*scale; q2[9]=c.y*scale; q2[10]=c.z*scale; q2[11]=c.w*scale;
    }
    float o1[12], o2[12];
#pragma unroll
    for (int i = 0; i < 12; i++) { o1[i] = 0.f; o2[i] = 0.f; }
    float d1 = 0.f, d2 = 0.f;

    const int full = 2 * qt;              // tiles fully below both queries
    const int last = full + 1;

    prefetch(0, 0);
    cp_wait0();
    __syncthreads();

    int buf = 0;
    for (int kt = 0; kt <= last; kt++) {
        if (kt < last) prefetch(kt + 1, buf ^ 1);
        const float4* sk = s_k[buf];
        const float4* sv = s_v[buf];
        if      (kt <  full) attn_tile2<0>(sk, sv, t, q1, q2, o1, o2, d1, d2);
        else if (kt == full) attn_tile2<1>(sk, sv, t, q1, q2, o1, o2, d1, d2);
        else                 attn_tile2<2>(sk, sv, t, q1, q2, o1, o2, d1, d2);
        cp_wait0();
        __syncthreads();
        buf ^= 1;
    }

    float i1 = 1.f / d1, i2 = 1.f / d2;
    float4* out1 = (float4*)(g_ctx + (((size_t)bb * Lc + l1) * Hc + h) * Kc);
    float4* out2 = (float4*)(g_ctx + (((size_t)bb * Lc + l2) * Hc + h) * Kc);
    out1[0] = make_float4(o1[0]*i1, o1[1]*i1, o1[2]*i1,  o1[3]*i1);
    out1[1] = make_float4(o1[4]*i1, o1[5]*i1, o1[6]*i1,  o1[7]*i1);
    out1[2] = make_float4(o1[8]*i1, o1[9]*i1, o1[10]*i1, o1[11]*i1);
    out2[0] = make_float4(o2[0]*i2, o2[1]*i2, o2[2]*i2,  o2[3]*i2);
    out2[1] = make_float4(o2[4]*i2, o2[5]*i2, o2[6]*i2,  o2[7]*i2);
    out2[2] = make_float4(o2[8]*i2, o2[9]*i2, o2[10]*i2, o2[11]*i2);
}

// ---------------- output projection + residual + fused LN2: tf32 MMA ----------
#define PA_S 52
#define PB_S 200
#define PA_FLOATS (64 * PA_S)
#define PB_FLOATS (48 * PB_S)
#define PST_S 196
#define PROJ_SMEM_BYTES ((PA_FLOATS + PB_FLOATS) * 4)   // 12928 floats > 64*196

__global__ __launch_bounds__(256, 4)
void proj_mma_kernel(const float* __restrict__ x,
                     const float* __restrict__ wo,
                     const float* __restrict__ bo,
                     const float* __restrict__ ln_g,
                     const float* __restrict__ ln_b)
{
    extern __shared__ float smem[];
    float* sA = smem;                 // [64][52]  ctx rows, tf32
    float* sB = smem + PA_FLOATS;     // [48][200] wo, tf32

    const int tid  = threadIdx.x;
    const int w    = tid >> 5;
    const int lane = tid & 31;
    const int tig  = lane & 3;
    const int grp  = lane >> 2;
    const int rowbase = blockIdx.x * 64;

    for (int idx = tid; idx < 64 * 12; idx += 256) {
        int r = idx / 12, c4 = (idx % 12) * 4;
        float4 v = *(const float4*)(g_ctx + (size_t)(rowbase + r) * 48 + c4);
        float* d = sA + r * PA_S + c4;
        d[0] = to_tf32(v.x); d[1] = to_tf32(v.y);
        d[2] = to_tf32(v.z); d[3] = to_tf32(v.w);
    }
    for (int idx = tid; idx < 48 * 48; idx += 256) {
        int r = idx / 48, c4 = (idx % 48) * 4;
        float4 v = *(const float4*)(wo + (size_t)r * Dc + c4);
        float* d = sB + r * PB_S + c4;
        d[0] = to_tf32(v.x); d[1] = to_tf32(v.y);
        d[2] = to_tf32(v.z); d[3] = to_tf32(v.w);
    }
    __syncthreads();

    const int mbase = (w & 1) * 32;
    const int nbase = (w >> 1) * 48;
    float c[2][6][4];
#pragma unroll
    for (int i = 0; i < 2; i++)
#pragma unroll
        for (int j = 0; j < 6; j++)
#pragma unroll
            for (int q = 0; q < 4; q++) c[i][j][q] = 0.f;

#pragma unroll
    for (int ks = 0; ks < 6; ks++) {
        const int c0 = ks * 8;
        uint32_t a[2][4];
#pragma unroll
        for (int mt = 0; mt < 2; mt++) {
            const float* ap = sA + (mbase + mt * 16 + grp) * PA_S + c0 + tig;
            a[mt][0] = __float_as_uint(ap[0]);
            a[mt][1] = __float_as_uint(ap[8 * PA_S]);
            a[mt][2] = __float_as_uint(ap[4]);
            a[mt][3] = __float_as_uint(ap[8 * PA_S + 4]);
        }
        const float* bp = sB + (c0 + tig) * PB_S + nbase + grp;
#pragma unroll
        for (int nt = 0; nt < 6; nt++) {
            uint32_t b0 = __float_as_uint(bp[nt * 8]);
            uint32_t b1 = __float_as_uint(bp[nt * 8 + 4 * PB_S]);
            mma_tf32(c[0][nt], a[0], b0, b1);
            mma_tf32(c[1][nt], a[1], b0, b1);
        }
    }
    __syncthreads();                       // done with sA/sB; reuse as stage

    float* stage = smem;                   // [64][196]
#pragma unroll
    for (int mt = 0; mt < 2; mt++) {
#pragma unroll
        for (int rs = 0; rs < 2; rs++) {
            int r = mbase + mt * 16 + grp + rs * 8;
            size_t off = (size_t)(rowbase + r) * Dc;
#pragma unroll
            for (int nt = 0; nt < 6; nt++) {
                int n = nbase + nt * 8 + tig * 2;
                float2 xv = *(const float2*)(x + off + n);
                float2 res;
                res.x = c[mt][nt][rs * 2 + 0] + bo[n]     + xv.x;
                res.y = c[mt][nt][rs * 2 + 1] + bo[n + 1] + xv.y;
                *(float2*)(g_y1 + off + n) = res;
                *(float2*)(stage + r * PST_S + n) = res;
            }
        }
    }
    __syncthreads();

    // fused LN2: warp w handles rows w, w+8, ... -> g_xn (fp32)
    for (int r = w; r < 64; r += 8) {
        float vv[6]; float s = 0.f;
#pragma unroll
        for (int i = 0; i < 6; i++) { vv[i] = stage[r * PST_S + lane + 32*i]; s += vv[i]; }
#pragma unroll
        for (int o = 16; o; o >>= 1) s += __shfl_xor_sync(0xffffffffu, s, o);
        float mean = s * (1.f/192.f);
        float vs = 0.f;
#pragma unroll
        for (int i = 0; i < 6; i++) { float dd = vv[i] - mean; vs += dd*dd; }
#pragma unroll
        for (int o = 16; o; o >>= 1) vs += __shfl_xor_sync(0xffffffffu, vs, o);
        float inv = rsqrtf(vs * (1.f/192.f) + 1e-3f);
#pragma unroll
        for (int i = 0; i < 6; i++) {
            int cc = lane + 32*i;
            g_xn[(size_t)(rowbase + r) * Dc + cc] =
                (vv[i] - mean) * inv * ln_g[cc] + ln_b[cc];
        }
    }
}

// ---------------- conv1d as tf32 tensor-core GEMM ----------------
#define SA_STRIDE 196
#define SB_STRIDE 200
#define SA_FLOATS (66 * SA_STRIDE)
#define SB_FLOATS (32 * SB_STRIDE)
#define CONV_SMEM_BYTES ((SA_FLOATS + 2 * SB_FLOATS) * 4)

template<int MODE>
__global__ __launch_bounds__(256, 2)
void conv_mma_kernel(const float* __restrict__ W,
                     const float* __restrict__ bias,
                     float* __restrict__ out)
{
    extern __shared__ float smem[];
    float* sA = smem;                    // [66][196]
    float* sB = smem + SA_FLOATS;        // [2][32][200]

    const int tid  = threadIdx.x;
    const int w    = tid >> 5;
    const int lane = tid & 31;
    const int tig  = lane & 3;
    const int grp  = lane >> 2;
    const int l0   = blockIdx.x * 64;
    const int bb   = blockIdx.y;
    const float* srcb = ((MODE == 0) ? g_xn : g_h) + (size_t)bb * Lc * Dc;

    for (int idx = tid; idx < 66 * 48; idx += 256) {
        int r = idx / 48, c4 = (idx % 48) * 4;
        int l = l0 - 1 + r; l = l < 0 ? 0 : (l > Lc - 1 ? Lc - 1 : l);
        float4 v = *(const float4*)(srcb + (size_t)l * Dc + c4);
        float* d = sA + r * SA_STRIDE + c4;
        d[0] = to_tf32(v.x); d[1] = to_tf32(v.y);
        d[2] = to_tf32(v.z); d[3] = to_tf32(v.w);
    }

    const int mbase = (w & 1) * 32;
    const int nbase = (w >> 1) * 48;
    float c[2][6][4];
#pragma unroll
    for (int i = 0; i < 2; i++)
#pragma unroll
        for (int j = 0; j < 6; j++)
#pragma unroll
            for (int q = 0; q < 4; q++) c[i][j][q] = 0.f;

    auto loadW = [&](int kc, int bf) {
        float* dstb = sB + bf * SB_FLOATS;
#pragma unroll
        for (int it = 0; it < 6; it++) {
            int idx = tid + it * 256;
            int k = idx / 48, c4 = (idx % 48) * 4;
            float4 v = *(const float4*)(W + ((size_t)(kc * 32 + k)) * Dc + c4);
            float* d = dstb + k * SB_STRIDE + c4;
            d[0] = to_tf32(v.x); d[1] = to_tf32(v.y);
            d[2] = to_tf32(v.z); d[3] = to_tf32(v.w);
        }
    };

    loadW(0, 0);
    __syncthreads();

    int buf = 0;
    for (int kc = 0; kc < 18; kc++) {
        if (kc < 17) loadW(kc + 1, buf ^ 1);
        const int t  = kc / 6;
        const int cc = (kc % 6) * 32;
        const float* bBuf = sB + buf * SB_FLOATS;
#pragma unroll
        for (int ks = 0; ks < 4; ks++) {
            const int c0 = cc + ks * 8;
            uint32_t a[2][4];
#pragma unroll
            for (int mt = 0; mt < 2; mt++) {
                const float* ap = sA + (mbase + mt * 16 + grp + t) * SA_STRIDE + c0 + tig;
                a[mt][0] = __float_as_uint(ap[0]);
                a[mt][1] = __float_as_uint(ap[8 * SA_STRIDE]);
                a[mt][2] = __float_as_uint(ap[4]);
                a[mt][3] = __float_as_uint(ap[8 * SA_STRIDE + 4]);
            }
            const float* bp = bBuf + (ks * 8 + tig) * SB_STRIDE + nbase + grp;
#pragma unroll
            for (int nt = 0; nt < 6; nt++) {
                uint32_t b0 = __float_as_uint(bp[nt * 8]);
                uint32_t b1 = __float_as_uint(bp[nt * 8 + 4 * SB_STRIDE]);
                mma_tf32(c[0][nt], a[0], b0, b1);
                mma_tf32(c[1][nt], a[1], b0, b1);
            }
        }
        __syncthreads();
        buf ^= 1;
    }

    float* dst = (MODE == 0) ? g_h : out;
#pragma unroll
    for (int mt = 0; mt < 2; mt++) {
#pragma unroll
        for (int rs = 0; rs < 2; rs++) {
            int l = l0 + mbase + mt * 16 + grp + rs * 8;
            bool interior = (l >= 1) && (l <= Lc - 2);
            size_t rowoff = ((size_t)bb * Lc + l) * Dc;
#pragma unroll
            for (int nt = 0; nt < 6; nt++) {
                int n = nbase + nt * 8 + tig * 2;
                float v0 = c[mt][nt][rs * 2 + 0] + bias[n];
                float v1 = c[mt][nt][rs * 2 + 1] + bias[n + 1];
                float2 res;
                if (MODE == 0) {
                    res.x = interior ? fmaxf(v0, 0.f) : 0.f;
                    res.y = interior ? fmaxf(v1, 0.f) : 0.f;
                } else {
                    float2 y = *(const float2*)(g_y1 + rowoff + n);
                    res.x = y.x + (interior ? v0 : 0.f);
                    res.y = y.y + (interior ? v1 : 0.f);
                }
                *(float2*)(dst + rowoff + n) = res;
            }
        }
    }
}

// ---------------- launcher ----------------
extern "C" void kernel_launch(void* const* d_in, const int* in_sizes, int n_in,
                              void* d_out, int out_size)
{
    const float* x     = (const float*)d_in[0];
    const float* ln1_g = (const float*)d_in[1];
    const float* ln1_b = (const float*)d_in[2];
    const float* wq    = (const float*)d_in[3];
    const float* bq    = (const float*)d_in[4];
    const float* wk    = (const float*)d_in[5];
    const float* bk    = (const float*)d_in[6];
    const float* wv    = (const float*)d_in[7];
    const float* bv    = (const float*)d_in[8];
    const float* wo    = (const float*)d_in[9];
    const float* bo    = (const float*)d_in[10];
    const float* ln2_g = (const float*)d_in[11];
    const float* ln2_b = (const float*)d_in[12];
    const float* c1_w  = (const float*)d_in[13];
    const float* c1_b  = (const float*)d_in[14];
    const float* c2_w  = (const float*)d_in[15];
    const float* c2_b  = (const float*)d_in[16];
    float* outp = (float*)d_out;

    cudaFuncSetAttribute(conv_mma_kernel<0>,
                         cudaFuncAttributeMaxDynamicSharedMemorySize, CONV_SMEM_BYTES);
    cudaFuncSetAttribute(conv_mma_kernel<1>,
                         cudaFuncAttributeMaxDynamicSharedMemorySize, CONV_SMEM_BYTES);
    cudaFuncSetAttribute(qkv_mma_kernel,
                         cudaFuncAttributeMaxDynamicSharedMemorySize, QKV_SMEM_BYTES);
    cudaFuncSetAttribute(proj_mma_kernel,
                         cudaFuncAttributeMaxDynamicSharedMemorySize, PROJ_SMEM_BYTES);

    qkv_mma_kernel<<<(Bc*Lc)/64, 192, QKV_SMEM_BYTES>>>(x, ln1_g, ln1_b,
                                                        wq, bq, wk, bk, wv, bv);
    attn_kernel<<<dim3(Lc/256, Hc, Bc), 128>>>();
    proj_mma_kernel<<<(Bc*Lc)/64, 256, PROJ_SMEM_BYTES>>>(x, wo, bo, ln2_g, ln2_b);
    conv_mma_kernel<0><<<dim3(Lc/64, Bc), 256, CONV_SMEM_BYTES>>>(c1_w, c1_b, outp);
    conv_mma_kernel<1><<<dim3(Lc/64, Bc), 256, CONV_SMEM_BYTES>>>(c2_w, c2_b, outp);
}

// round 10
// speedup vs baseline: 1.6493x; 1.6493x over previous
#include <cuda_runtime.h>
#include <math.h>
#include <stdint.h>

#define Bc 16
#define Lc 2048
#define Dc 192
#define Hc 4
#define Kc 12

// ---------------- scratch (no allocations allowed) ----------------
__device__ float g_xn [(size_t)Bc*Lc*Dc];       // xn2 (written by fused proj+LN2)
__device__ float g_q  [(size_t)Bc*Hc*Lc*Kc];    // [B,H,L,K]
__device__ float g_k  [(size_t)Bc*Hc*Lc*Kc];
__device__ float g_v  [(size_t)Bc*Hc*Lc*Kc];
__device__ float g_ctx[(size_t)Bc*Lc*Hc*Kc];    // [B,L,H,K]
__device__ float g_y1 [(size_t)Bc*Lc*Dc];       // x + MHA
__device__ float g_h  [(size_t)Bc*Lc*Dc];       // relu(conv1), zero rows 0, L-1

__device__ __forceinline__ float ex2(float x) {
    float y; asm("ex2.approx.f32 %0, %1;" : "=f"(y) : "f"(x)); return y;
}
__device__ __forceinline__ float to_tf32(float x) {
    uint32_t u; asm("cvt.rna.tf32.f32 %0, %1;" : "=r"(u) : "f"(x));
    return __uint_as_float(u);
}
__device__ __forceinline__ void mma_tf32(float* c, const uint32_t* a,
                                         uint32_t b0, uint32_t b1)
{
    asm volatile(
        "mma.sync.aligned.m16n8k8.row.col.f32.tf32.tf32.f32 "
        "{%0,%1,%2,%3}, {%4,%5,%6,%7}, {%8,%9}, {%0,%1,%2,%3};"
        : "+f"(c[0]), "+f"(c[1]), "+f"(c[2]), "+f"(c[3])
        : "r"(a[0]), "r"(a[1]), "r"(a[2]), "r"(a[3]), "r"(b0), "r"(b1));
}

// ---------------- QKV projection + fused LN1: tf32 MMA ----------------
// M=64/block, N=3x48, K=192. 192 threads = 6 warps.
#define QA_S 196
#define QB_S 152
#define QA_FLOATS (64 * QA_S)
#define QB_FLOATS (32 * QB_S)
#define QKV_SMEM_BYTES ((QA_FLOATS + 2 * QB_FLOATS) * 4)

__global__ __launch_bounds__(192, 2)
void qkv_mma_kernel(const float* __restrict__ x,
                    const float* __restrict__ ln_g, const float* __restrict__ ln_b,
                    const float* __restrict__ wq, const float* __restrict__ bq,
                    const float* __restrict__ wk, const float* __restrict__ bk,
                    const float* __restrict__ wv, const float* __restrict__ bv)
{
    extern __shared__ float smem[];
    float* sA = smem;                 // [64][196] raw x rows -> LN'd tf32 in-place
    float* sB = smem + QA_FLOATS;     // [2][32][152] tf32 weights (q|k|v cols)

    const int tid  = threadIdx.x;
    const int w    = tid >> 5;
    const int lane = tid & 31;
    const int tig  = lane & 3;
    const int grp  = lane >> 2;
    const int rowbase = blockIdx.x * 64;
    const int bb   = rowbase / Lc;
    const int lloc = rowbase % Lc;

    auto loadW = [&](int kc, int bf) {
        float* dstb = sB + bf * QB_FLOATS;
#pragma unroll
        for (int it = 0; it < 6; it++) {
            int idx = tid + it * 192;            // 32*36 float4 = 1152
            int k = idx / 36, c = (idx % 36) * 4;
            int m = c / 48, lc = c % 48;
            const float* src = (m == 0) ? wq : (m == 1) ? wk : wv;
            float4 v = *(const float4*)(src + (size_t)(kc * 32 + k) * 48 + lc);
            float* d = dstb + k * QB_S + c;
            d[0] = to_tf32(v.x); d[1] = to_tf32(v.y);
            d[2] = to_tf32(v.z); d[3] = to_tf32(v.w);
        }
    };

    for (int idx = tid; idx < 64 * 48; idx += 192) {
        int r = idx / 48, c4 = (idx % 48) * 4;
        *(float4*)(sA + r * QA_S + c4) =
            *(const float4*)(x + (size_t)(rowbase + r) * Dc + c4);
    }
    loadW(0, 0);
    __syncthreads();

    // fused LN1: warp w handles rows w, w+6, ...
    for (int r = w; r < 64; r += 6) {
        float vv[6]; float s = 0.f;
#pragma unroll
        for (int i = 0; i < 6; i++) { vv[i] = sA[r * QA_S + lane + 32*i]; s += vv[i]; }
#pragma unroll
        for (int o = 16; o; o >>= 1) s += __shfl_xor_sync(0xffffffffu, s, o);
        float mean = s * (1.f/192.f);
        float vs = 0.f;
#pragma unroll
        for (int i = 0; i < 6; i++) { float dd = vv[i] - mean; vs += dd*dd; }
#pragma unroll
        for (int o = 16; o; o >>= 1) vs += __shfl_xor_sync(0xffffffffu, vs, o);
        float inv = rsqrtf(vs * (1.f/192.f) + 1e-3f);
#pragma unroll
        for (int i = 0; i < 6; i++) {
            int c = lane + 32*i;
            sA[r * QA_S + c] = to_tf32((vv[i] - mean) * inv * ln_g[c] + ln_b[c]);
        }
    }
    __syncthreads();

    const int s     = w >> 1;
    const int mbase = (w & 1) * 32;
    float c[2][6][4];
#pragma unroll
    for (int i = 0; i < 2; i++)
#pragma unroll
        for (int j = 0; j < 6; j++)
#pragma unroll
            for (int q = 0; q < 4; q++) c[i][j][q] = 0.f;

    int buf = 0;
    for (int kc = 0; kc < 6; kc++) {
        if (kc < 5) loadW(kc + 1, buf ^ 1);
        const float* bBuf = sB + buf * QB_FLOATS + s * 48;
#pragma unroll
        for (int ks = 0; ks < 4; ks++) {
            const int c0 = kc * 32 + ks * 8;
            uint32_t a[2][4];
#pragma unroll
            for (int mt = 0; mt < 2; mt++) {
                const float* ap = sA + (mbase + mt * 16 + grp) * QA_S + c0 + tig;
                a[mt][0] = __float_as_uint(ap[0]);
                a[mt][1] = __float_as_uint(ap[8 * QA_S]);
                a[mt][2] = __float_as_uint(ap[4]);
                a[mt][3] = __float_as_uint(ap[8 * QA_S + 4]);
            }
            const float* bp = bBuf + (ks * 8 + tig) * QB_S + grp;
#pragma unroll
            for (int nt = 0; nt < 6; nt++) {
                uint32_t b0 = __float_as_uint(bp[nt * 8]);
                uint32_t b1 = __float_as_uint(bp[nt * 8 + 4 * QB_S]);
                mma_tf32(c[0][nt], a[0], b0, b1);
                mma_tf32(c[1][nt], a[1], b0, b1);
            }
        }
        __syncthreads();
        buf ^= 1;
    }

    const float* Bp = (s == 0) ? bq : (s == 1) ? bk : bv;
    float* O = (s == 0) ? g_q : (s == 1) ? g_k : g_v;
#pragma unroll
    for (int mt = 0; mt < 2; mt++) {
#pragma unroll
        for (int rs = 0; rs < 2; rs++) {
            int l = lloc + mbase + mt * 16 + grp + rs * 8;
#pragma unroll
            for (int nt = 0; nt < 6; nt++) {
                int n = nt * 8 + tig * 2;       // 0..47, even
                int h = n / 12, kk = n % 12;
                float2 res;
                res.x = c[mt][nt][rs * 2 + 0] + Bp[n];
                res.y = c[mt][nt][rs * 2 + 1] + Bp[n + 1];
                *(float2*)(O + (((size_t)bb * Hc + h) * Lc + l) * Kc + kk) = res;
            }
        }
    }
}

// ---------------- causal attention: 2 queries/thread, 256 threads/block -------
// block covers 512 queries: l1 = 512*qt + t (t in 0..255), l2 = l1 + 256.
// Modes per query: 0 = FULL, 1 = LIMIT (mm <= lim), 2 = SKIP.
template<int M1, int M2>
__device__ __forceinline__ void attn_tile2(const float4* __restrict__ sk,
                                           const float4* __restrict__ sv,
                                           int lim1, int lim2,
                                           const float* q1, const float* q2,
                                           float* o1, float* o2,
                                           float& d1, float& d2)
{
#pragma unroll 4
    for (int mm = 0; mm < 128; mm++) {
        float4 ka = sk[3*mm], kb = sk[3*mm+1], kc = sk[3*mm+2];
        float p1 = 0.f, p2 = 0.f;
        if (M1 < 2) {
            float s1 = q1[0]*ka.x + q1[1]*ka.y + q1[2]*ka.z + q1[3]*ka.w
                     + q1[4]*kb.x + q1[5]*kb.y + q1[6]*kb.z + q1[7]*kb.w
                     + q1[8]*kc.x + q1[9]*kc.y + q1[10]*kc.z + q1[11]*kc.w;
            p1 = ex2(s1);
            if (M1 == 1 && mm > lim1) p1 = 0.f;
            d1 += p1;
        }
        if (M2 < 2) {
            float s2 = q2[0]*ka.x + q2[1]*ka.y + q2[2]*ka.z + q2[3]*ka.w
                     + q2[4]*kb.x + q2[5]*kb.y + q2[6]*kb.z + q2[7]*kb.w
                     + q2[8]*kc.x + q2[9]*kc.y + q2[10]*kc.z + q2[11]*kc.w;
            p2 = ex2(s2);
            if (M2 == 1 && mm > lim2) p2 = 0.f;
            d2 += p2;
        }
        float4 va = sv[3*mm], vb = sv[3*mm+1], vc = sv[3*mm+2];
        if (M1 < 2) {
            o1[0] += p1*va.x; o1[1] += p1*va.y; o1[2]  += p1*va.z; o1[3]  += p1*va.w;
            o1[4] += p1*vb.x; o1[5] += p1*vb.y; o1[6]  += p1*vb.z; o1[7]  += p1*vb.w;
            o1[8] += p1*vc.x; o1[9] += p1*vc.y; o1[10] += p1*vc.z; o1[11] += p1*vc.w;
        }
        if (M2 < 2) {
            o2[0] += p2*va.x; o2[1] += p2*va.y; o2[2]  += p2*va.z; o2[3]  += p2*va.w;
            o2[4] += p2*vb.x; o2[5] += p2*vb.y; o2[6]  += p2*vb.z; o2[7]  += p2*vb.w;
            o2[8] += p2*vc.x; o2[9] += p2*vc.y; o2[10] += p2*vc.z; o2[11] += p2*vc.w;
        }
    }
}

__global__ __launch_bounds__(256)
void attn_kernel()
{
    __shared__ float4 sk[128 * 3];
    __shared__ float4 sv[128 * 3];
    int qt = gridDim.x - 1 - blockIdx.x;    // heavy tiles first
    int h = blockIdx.y, bb = blockIdx.z;
    int t = threadIdx.x;                    // 0..255
    int l1 = qt * 512 + t;
    int l2 = l1 + 256;

    size_t head = ((size_t)bb * Hc + h) * Lc * Kc;
    const float4* qb = (const float4*)(g_q + head);
    const float*  kb = g_k + head;
    const float*  vb = g_v + head;

    const float scale = 0.4164682333693345f;   // log2(e)/sqrt(12)
    float q1[12], q2[12];
    {
        float4 a = qb[3*l1], b = qb[3*l1+1], c = qb[3*l1+2];
        q1[0]=a.x*scale; q1[1]=a.y*scale; q1[2]=a.z*scale; q1[3]=a.w*scale;
        q1[4]=b.x*scale; q1[5]=b.y*scale; q1[6]=b.z*scale; q1[7]=b.w*scale;
        q1[8]=c.x*scale; q1[9]=c.y*scale; q1[10]=c.z*scale; q1[11]=c.w*scale;
        a = qb[3*l2]; b = qb[3*l2+1]; c = qb[3*l2+2];
        q2[0]=a.x*scale; q2[1]=a.y*scale; q2[2]=a.z*scale; q2[3]=a.w*scale;
        q2[4]=b.x*scale; q2[5]=b.y*scale; q2[6]=b.z*scale; q2[7]=b.w*scale;
        q2[8]=c.x*scale; q2[9]=c.y*scale; q2[10]=c.z*scale; q2[11]=c.w*scale;
    }
    float o1[12], o2[12];
#pragma unroll
    for (int i = 0; i < 12; i++) { o1[i] = 0.f; o2[i] = 0.f; }
    float d1 = 0.f, d2 = 0.f;

    const int full = 4 * qt;    // tiles with all keys < 512*qt <= both queries
    for (int kt = 0; kt < full + 4; kt++) {
        __syncthreads();
        const float4* ks = (const float4*)(kb + (size_t)kt * 128 * Kc);
        const float4* vs = (const float4*)(vb + (size_t)kt * 128 * Kc);
        for (int i = t; i < 128 * 3; i += 256) { sk[i] = ks[i]; sv[i] = vs[i]; }
        __syncthreads();
        int j = kt - full;
        if      (kt < full) attn_tile2<0,0>(sk, sv, 0, 0, q1, q2, o1, o2, d1, d2);
        else if (j == 0)    attn_tile2<1,0>(sk, sv, t,       0,     q1, q2, o1, o2, d1, d2);
        else if (j == 1)    attn_tile2<1,0>(sk, sv, t - 128, 0,     q1, q2, o1, o2, d1, d2);
        else if (j == 2)    attn_tile2<2,1>(sk, sv, 0,       t,     q1, q2, o1, o2, d1, d2);
        else                attn_tile2<2,1>(sk, sv, 0,       t-128, q1, q2, o1, o2, d1, d2);
    }

    float i1 = 1.f / d1, i2 = 1.f / d2;
    float4* out1 = (float4*)(g_ctx + (((size_t)bb * Lc + l1) * Hc + h) * Kc);
    float4* out2 = (float4*)(g_ctx + (((size_t)bb * Lc + l2) * Hc + h) * Kc);
    out1[0] = make_float4(o1[0]*i1, o1[1]*i1, o1[2]*i1,  o1[3]*i1);
    out1[1] = make_float4(o1[4]*i1, o1[5]*i1, o1[6]*i1,  o1[7]*i1);
    out1[2] = make_float4(o1[8]*i1, o1[9]*i1, o1[10]*i1, o1[11]*i1);
    out2[0] = make_float4(o2[0]*i2, o2[1]*i2, o2[2]*i2,  o2[3]*i2);
    out2[1] = make_float4(o2[4]*i2, o2[5]*i2, o2[6]*i2,  o2[7]*i2);
    out2[2] = make_float4(o2[8]*i2, o2[9]*i2, o2[10]*i2, o2[11]*i2);
}

// ---------------- output projection + residual + fused LN2: tf32 MMA ----------
#define PA_S 52
#define PB_S 200
#define PA_FLOATS (64 * PA_S)
#define PB_FLOATS (48 * PB_S)
#define PST_S 196
#define PROJ_SMEM_BYTES ((PA_FLOATS + PB_FLOATS) * 4)   // 12928 floats > 64*196

__global__ __launch_bounds__(256, 4)
void proj_mma_kernel(const float* __restrict__ x,
                     const float* __restrict__ wo,
                     const float* __restrict__ bo,
                     const float* __restrict__ ln_g,
                     const float* __restrict__ ln_b)
{
    extern __shared__ float smem[];
    float* sA = smem;                 // [64][52]  ctx rows, tf32
    float* sB = smem + PA_FLOATS;     // [48][200] wo, tf32

    const int tid  = threadIdx.x;
    const int w    = tid >> 5;
    const int lane = tid & 31;
    const int tig  = lane & 3;
    const int grp  = lane >> 2;
    const int rowbase = blockIdx.x * 64;

    for (int idx = tid; idx < 64 * 12; idx += 256) {
        int r = idx / 12, c4 = (idx % 12) * 4;
        float4 v = *(const float4*)(g_ctx + (size_t)(rowbase + r) * 48 + c4);
        float* d = sA + r * PA_S + c4;
        d[0] = to_tf32(v.x); d[1] = to_tf32(v.y);
        d[2] = to_tf32(v.z); d[3] = to_tf32(v.w);
    }
    for (int idx = tid; idx < 48 * 48; idx += 256) {
        int r = idx / 48, c4 = (idx % 48) * 4;
        float4 v = *(const float4*)(wo + (size_t)r * Dc + c4);
        float* d = sB + r * PB_S + c4;
        d[0] = to_tf32(v.x); d[1] = to_tf32(v.y);
        d[2] = to_tf32(v.z); d[3] = to_tf32(v.w);
    }
    __syncthreads();

    const int mbase = (w & 1) * 32;
    const int nbase = (w >> 1) * 48;
    float c[2][6][4];
#pragma unroll
    for (int i = 0; i < 2; i++)
#pragma unroll
        for (int j = 0; j < 6; j++)
#pragma unroll
            for (int q = 0; q < 4; q++) c[i][j][q] = 0.f;

#pragma unroll
    for (int ks = 0; ks < 6; ks++) {
        const int c0 = ks * 8;
        uint32_t a[2][4];
#pragma unroll
        for (int mt = 0; mt < 2; mt++) {
            const float* ap = sA + (mbase + mt * 16 + grp) * PA_S + c0 + tig;
            a[mt][0] = __float_as_uint(ap[0]);
            a[mt][1] = __float_as_uint(ap[8 * PA_S]);
            a[mt][2] = __float_as_uint(ap[4]);
            a[mt][3] = __float_as_uint(ap[8 * PA_S + 4]);
        }
        const float* bp = sB + (c0 + tig) * PB_S + nbase + grp;
#pragma unroll
        for (int nt = 0; nt < 6; nt++) {
            uint32_t b0 = __float_as_uint(bp[nt * 8]);
            uint32_t b1 = __float_as_uint(bp[nt * 8 + 4 * PB_S]);
            mma_tf32(c[0][nt], a[0], b0, b1);
            mma_tf32(c[1][nt], a[1], b0, b1);
        }
    }
    __syncthreads();                       // done with sA/sB; reuse as stage

    float* stage = smem;                   // [64][196]
#pragma unroll
    for (int mt = 0; mt < 2; mt++) {
#pragma unroll
        for (int rs = 0; rs < 2; rs++) {
            int r = mbase + mt * 16 + grp + rs * 8;
            size_t off = (size_t)(rowbase + r) * Dc;
#pragma unroll
            for (int nt = 0; nt < 6; nt++) {
                int n = nbase + nt * 8 + tig * 2;
                float2 xv = *(const float2*)(x + off + n);
                float2 res;
                res.x = c[mt][nt][rs * 2 + 0] + bo[n]     + xv.x;
                res.y = c[mt][nt][rs * 2 + 1] + bo[n + 1] + xv.y;
                *(float2*)(g_y1 + off + n) = res;
                *(float2*)(stage + r * PST_S + n) = res;
            }
        }
    }
    __syncthreads();

    // fused LN2: warp w handles rows w, w+8, ... -> g_xn (fp32)
    for (int r = w; r < 64; r += 8) {
        float vv[6]; float s = 0.f;
#pragma unroll
        for (int i = 0; i < 6; i++) { vv[i] = stage[r * PST_S + lane + 32*i]; s += vv[i]; }
#pragma unroll
        for (int o = 16; o; o >>= 1) s += __shfl_xor_sync(0xffffffffu, s, o);
        float mean = s * (1.f/192.f);
        float vs = 0.f;
#pragma unroll
        for (int i = 0; i < 6; i++) { float dd = vv[i] - mean; vs += dd*dd; }
#pragma unroll
        for (int o = 16; o; o >>= 1) vs += __shfl_xor_sync(0xffffffffu, vs, o);
        float inv = rsqrtf(vs * (1.f/192.f) + 1e-3f);
#pragma unroll
        for (int i = 0; i < 6; i++) {
            int cc = lane + 32*i;
            g_xn[(size_t)(rowbase + r) * Dc + cc] =
                (vv[i] - mean) * inv * ln_g[cc] + ln_b[cc];
        }
    }
}

// ---------------- conv1d as tf32 tensor-core GEMM ----------------
#define SA_STRIDE 196
#define SB_STRIDE 200
#define SA_FLOATS (66 * SA_STRIDE)
#define SB_FLOATS (32 * SB_STRIDE)
#define CONV_SMEM_BYTES ((SA_FLOATS + 2 * SB_FLOATS) * 4)

template<int MODE>
__global__ __launch_bounds__(256, 2)
void conv_mma_kernel(const float* __restrict__ W,
                     const float* __restrict__ bias,
                     float* __restrict__ out)
{
    extern __shared__ float smem[];
    float* sA = smem;                    // [66][196]
    float* sB = smem + SA_FLOATS;        // [2][32][200]

    const int tid  = threadIdx.x;
    const int w    = tid >> 5;
    const int lane = tid & 31;
    const int tig  = lane & 3;
    const int grp  = lane >> 2;
    const int l0   = blockIdx.x * 64;
    const int bb   = blockIdx.y;
    const float* srcb = ((MODE == 0) ? g_xn : g_h) + (size_t)bb * Lc * Dc;

    for (int idx = tid; idx < 66 * 48; idx += 256) {
        int r = idx / 48, c4 = (idx % 48) * 4;
        int l = l0 - 1 + r; l = l < 0 ? 0 : (l > Lc - 1 ? Lc - 1 : l);
        float4 v = *(const float4*)(srcb + (size_t)l * Dc + c4);
        float* d = sA + r * SA_STRIDE + c4;
        d[0] = to_tf32(v.x); d[1] = to_tf32(v.y);
        d[2] = to_tf32(v.z); d[3] = to_tf32(v.w);
    }

    const int mbase = (w & 1) * 32;
    const int nbase = (w >> 1) * 48;
    float c[2][6][4];
#pragma unroll
    for (int i = 0; i < 2; i++)
#pragma unroll
        for (int j = 0; j < 6; j++)
#pragma unroll
            for (int q = 0; q < 4; q++) c[i][j][q] = 0.f;

    auto loadW = [&](int kc, int bf) {
        float* dstb = sB + bf * SB_FLOATS;
#pragma unroll
        for (int it = 0; it < 6; it++) {
            int idx = tid + it * 256;
            int k = idx / 48, c4 = (idx % 48) * 4;
            float4 v = *(const float4*)(W + ((size_t)(kc * 32 + k)) * Dc + c4);
            float* d = dstb + k * SB_STRIDE + c4;
            d[0] = to_tf32(v.x); d[1] = to_tf32(v.y);
            d[2] = to_tf32(v.z); d[3] = to_tf32(v.w);
        }
    };

    loadW(0, 0);
    __syncthreads();

    int buf = 0;
    for (int kc = 0; kc < 18; kc++) {
        if (kc < 17) loadW(kc + 1, buf ^ 1);
        const int t  = kc / 6;
        const int cc = (kc % 6) * 32;
        const float* bBuf = sB + buf * SB_FLOATS;
#pragma unroll
        for (int ks = 0; ks < 4; ks++) {
            const int c0 = cc + ks * 8;
            uint32_t a[2][4];
#pragma unroll
            for (int mt = 0; mt < 2; mt++) {
                const float* ap = sA + (mbase + mt * 16 + grp + t) * SA_STRIDE + c0 + tig;
                a[mt][0] = __float_as_uint(ap[0]);
                a[mt][1] = __float_as_uint(ap[8 * SA_STRIDE]);
                a[mt][2] = __float_as_uint(ap[4]);
                a[mt][3] = __float_as_uint(ap[8 * SA_STRIDE + 4]);
            }
            const float* bp = bBuf + (ks * 8 + tig) * SB_STRIDE + nbase + grp;
#pragma unroll
            for (int nt = 0; nt < 6; nt++) {
                uint32_t b0 = __float_as_uint(bp[nt * 8]);
                uint32_t b1 = __float_as_uint(bp[nt * 8 + 4 * SB_STRIDE]);
                mma_tf32(c[0][nt], a[0], b0, b1);
                mma_tf32(c[1][nt], a[1], b0, b1);
            }
        }
        __syncthreads();
        buf ^= 1;
    }

    float* dst = (MODE == 0) ? g_h : out;
#pragma unroll
    for (int mt = 0; mt < 2; mt++) {
#pragma unroll
        for (int rs = 0; rs < 2; rs++) {
            int l = l0 + mbase + mt * 16 + grp + rs * 8;
            bool interior = (l >= 1) && (l <= Lc - 2);
            size_t rowoff = ((size_t)bb * Lc + l) * Dc;
#pragma unroll
            for (int nt = 0; nt < 6; nt++) {
                int n = nbase + nt * 8 + tig * 2;
                float v0 = c[mt][nt][rs * 2 + 0] + bias[n];
                float v1 = c[mt][nt][rs * 2 + 1] + bias[n + 1];
                float2 res;
                if (MODE == 0) {
                    res.x = interior ? fmaxf(v0, 0.f) : 0.f;
                    res.y = interior ? fmaxf(v1, 0.f) : 0.f;
                } else {
                    float2 y = *(const float2*)(g_y1 + rowoff + n);
                    res.x = y.x + (interior ? v0 : 0.f);
                    res.y = y.y + (interior ? v1 : 0.f);
                }
                *(float2*)(dst + rowoff + n) = res;
            }
        }
    }
}

// ---------------- launcher ----------------
extern "C" void kernel_launch(void* const* d_in, const int* in_sizes, int n_in,
                              void* d_out, int out_size)
{
    const float* x     = (const float*)d_in[0];
    const float* ln1_g = (const float*)d_in[1];
    const float* ln1_b = (const float*)d_in[2];
    const float* wq    = (const float*)d_in[3];
    const float* bq    = (const float*)d_in[4];
    const float* wk    = (const float*)d_in[5];
    const float* bk    = (const float*)d_in[6];
    const float* wv    = (const float*)d_in[7];
    const float* bv    = (const float*)d_in[8];
    const float* wo    = (const float*)d_in[9];
    const float* bo    = (const float*)d_in[10];
    const float* ln2_g = (const float*)d_in[11];
    const float* ln2_b = (const float*)d_in[12];
    const float* c1_w  = (const float*)d_in[13];
    const float* c1_b  = (const float*)d_in[14];
    const float* c2_w  = (const float*)d_in[15];
    const float* c2_b  = (const float*)d_in[16];
    float* outp = (float*)d_out;

    cudaFuncSetAttribute(conv_mma_kernel<0>,
                         cudaFuncAttributeMaxDynamicSharedMemorySize, CONV_SMEM_BYTES);
    cudaFuncSetAttribute(conv_mma_kernel<1>,
                         cudaFuncAttributeMaxDynamicSharedMemorySize, CONV_SMEM_BYTES);
    cudaFuncSetAttribute(qkv_mma_kernel,
                         cudaFuncAttributeMaxDynamicSharedMemorySize, QKV_SMEM_BYTES);
    cudaFuncSetAttribute(proj_mma_kernel,
                         cudaFuncAttributeMaxDynamicSharedMemorySize, PROJ_SMEM_BYTES);

    qkv_mma_kernel<<<(Bc*Lc)/64, 192, QKV_SMEM_BYTES>>>(x, ln1_g, ln1_b,
                                                        wq, bq, wk, bk, wv, bv);
    attn_kernel<<<dim3(Lc/512, Hc, Bc), 256>>>();
    proj_mma_kernel<<<(Bc*Lc)/64, 256, PROJ_SMEM_BYTES>>>(x, wo, bo, ln2_g, ln2_b);
    conv_mma_kernel<0><<<dim3(Lc/64, Bc), 256, CONV_SMEM_BYTES>>>(c1_w, c1_b, outp);
    conv_mma_kernel<1><<<dim3(Lc/64, Bc), 256, CONV_SMEM_BYTES>>>(c2_w, c2_b, outp);
}

// round 11
// speedup vs baseline: 2.4409x; 1.4800x over previous
#include <cuda_runtime.h>
#include <math.h>
#include <stdint.h>

#define Bc 16
#define Lc 2048
#define Dc 192
#define Hc 4
#define Kc 12

// ---------------- scratch (no allocations allowed) ----------------
__device__ float g_xn [(size_t)Bc*Lc*Dc];       // xn2 (written by fused proj+LN2)
__device__ float g_q  [(size_t)Bc*Hc*Lc*Kc];    // [B,H,L,K]
__device__ float g_k  [(size_t)Bc*Hc*Lc*Kc];
__device__ float g_v  [(size_t)Bc*Hc*Lc*Kc];
__device__ float g_ctx[(size_t)Bc*Lc*Hc*Kc];    // [B,L,H,K]
__device__ float g_y1 [(size_t)Bc*Lc*Dc];       // x + MHA
__device__ float g_h  [(size_t)Bc*Lc*Dc];       // relu(conv1), zero rows 0, L-1

__device__ __forceinline__ float ex2(float x) {
    float y; asm("ex2.approx.f32 %0, %1;" : "=f"(y) : "f"(x)); return y;
}
__device__ __forceinline__ float to_tf32(float x) {
    uint32_t u; asm("cvt.rna.tf32.f32 %0, %1;" : "=r"(u) : "f"(x));
    return __uint_as_float(u);
}
__device__ __forceinline__ uint32_t tf32b(float x) {
    uint32_t u; asm("cvt.rna.tf32.f32 %0, %1;" : "=r"(u) : "f"(x));
    return u;
}
__device__ __forceinline__ void mma_tf32(float* c, const uint32_t* a,
                                         uint32_t b0, uint32_t b1)
{
    asm volatile(
        "mma.sync.aligned.m16n8k8.row.col.f32.tf32.tf32.f32 "
        "{%0,%1,%2,%3}, {%4,%5,%6,%7}, {%8,%9}, {%0,%1,%2,%3};"
        : "+f"(c[0]), "+f"(c[1]), "+f"(c[2]), "+f"(c[3])
        : "r"(a[0]), "r"(a[1]), "r"(a[2]), "r"(a[3]), "r"(b0), "r"(b1));
}

// ---------------- QKV projection + fused LN1: tf32 MMA ----------------
// M=64/block, N=3x48, K=192. 192 threads = 6 warps.
#define QA_S 196
#define QB_S 152
#define QA_FLOATS (64 * QA_S)
#define QB_FLOATS (32 * QB_S)
#define QKV_SMEM_BYTES ((QA_FLOATS + 2 * QB_FLOATS) * 4)

__global__ __launch_bounds__(192, 2)
void qkv_mma_kernel(const float* __restrict__ x,
                    const float* __restrict__ ln_g, const float* __restrict__ ln_b,
                    const float* __restrict__ wq, const float* __restrict__ bq,
                    const float* __restrict__ wk, const float* __restrict__ bk,
                    const float* __restrict__ wv, const float* __restrict__ bv)
{
    extern __shared__ float smem[];
    float* sA = smem;                 // [64][196] raw x rows -> LN'd tf32 in-place
    float* sB = smem + QA_FLOATS;     // [2][32][152] tf32 weights (q|k|v cols)

    const int tid  = threadIdx.x;
    const int w    = tid >> 5;
    const int lane = tid & 31;
    const int tig  = lane & 3;
    const int grp  = lane >> 2;
    const int rowbase = blockIdx.x * 64;
    const int bb   = rowbase / Lc;
    const int lloc = rowbase % Lc;

    auto loadW = [&](int kc, int bf) {
        float* dstb = sB + bf * QB_FLOATS;
#pragma unroll
        for (int it = 0; it < 6; it++) {
            int idx = tid + it * 192;            // 32*36 float4 = 1152
            int k = idx / 36, c = (idx % 36) * 4;
            int m = c / 48, lc = c % 48;
            const float* src = (m == 0) ? wq : (m == 1) ? wk : wv;
            float4 v = *(const float4*)(src + (size_t)(kc * 32 + k) * 48 + lc);
            float* d = dstb + k * QB_S + c;
            d[0] = to_tf32(v.x); d[1] = to_tf32(v.y);
            d[2] = to_tf32(v.z); d[3] = to_tf32(v.w);
        }
    };

    for (int idx = tid; idx < 64 * 48; idx += 192) {
        int r = idx / 48, c4 = (idx % 48) * 4;
        *(float4*)(sA + r * QA_S + c4) =
            *(const float4*)(x + (size_t)(rowbase + r) * Dc + c4);
    }
    loadW(0, 0);
    __syncthreads();

    // fused LN1: warp w handles rows w, w+6, ...
    for (int r = w; r < 64; r += 6) {
        float vv[6]; float s = 0.f;
#pragma unroll
        for (int i = 0; i < 6; i++) { vv[i] = sA[r * QA_S + lane + 32*i]; s += vv[i]; }
#pragma unroll
        for (int o = 16; o; o >>= 1) s += __shfl_xor_sync(0xffffffffu, s, o);
        float mean = s * (1.f/192.f);
        float vs = 0.f;
#pragma unroll
        for (int i = 0; i < 6; i++) { float dd = vv[i] - mean; vs += dd*dd; }
#pragma unroll
        for (int o = 16; o; o >>= 1) vs += __shfl_xor_sync(0xffffffffu, vs, o);
        float inv = rsqrtf(vs * (1.f/192.f) + 1e-3f);
#pragma unroll
        for (int i = 0; i < 6; i++) {
            int c = lane + 32*i;
            sA[r * QA_S + c] = to_tf32((vv[i] - mean) * inv * ln_g[c] + ln_b[c]);
        }
    }
    __syncthreads();

    const int s     = w >> 1;
    const int mbase = (w & 1) * 32;
    float c[2][6][4];
#pragma unroll
    for (int i = 0; i < 2; i++)
#pragma unroll
        for (int j = 0; j < 6; j++)
#pragma unroll
            for (int q = 0; q < 4; q++) c[i][j][q] = 0.f;

    int buf = 0;
    for (int kc = 0; kc < 6; kc++) {
        if (kc < 5) loadW(kc + 1, buf ^ 1);
        const float* bBuf = sB + buf * QB_FLOATS + s * 48;
#pragma unroll
        for (int ks = 0; ks < 4; ks++) {
            const int c0 = kc * 32 + ks * 8;
            uint32_t a[2][4];
#pragma unroll
            for (int mt = 0; mt < 2; mt++) {
                const float* ap = sA + (mbase + mt * 16 + grp) * QA_S + c0 + tig;
                a[mt][0] = __float_as_uint(ap[0]);
                a[mt][1] = __float_as_uint(ap[8 * QA_S]);
                a[mt][2] = __float_as_uint(ap[4]);
                a[mt][3] = __float_as_uint(ap[8 * QA_S + 4]);
            }
            const float* bp = bBuf + (ks * 8 + tig) * QB_S + grp;
#pragma unroll
            for (int nt = 0; nt < 6; nt++) {
                uint32_t b0 = __float_as_uint(bp[nt * 8]);
                uint32_t b1 = __float_as_uint(bp[nt * 8 + 4 * QB_S]);
                mma_tf32(c[0][nt], a[0], b0, b1);
                mma_tf32(c[1][nt], a[1], b0, b1);
            }
        }
        __syncthreads();
        buf ^= 1;
    }

    const float* Bp = (s == 0) ? bq : (s == 1) ? bk : bv;
    float* O = (s == 0) ? g_q : (s == 1) ? g_k : g_v;
#pragma unroll
    for (int mt = 0; mt < 2; mt++) {
#pragma unroll
        for (int rs = 0; rs < 2; rs++) {
            int l = lloc + mbase + mt * 16 + grp + rs * 8;
#pragma unroll
            for (int nt = 0; nt < 6; nt++) {
                int n = nt * 8 + tig * 2;       // 0..47, even
                int h = n / 12, kk = n % 12;
                float2 res;
                res.x = c[mt][nt][rs * 2 + 0] + Bp[n];
                res.y = c[mt][nt][rs * 2 + 1] + Bp[n + 1];
                *(float2*)(O + (((size_t)bb * Hc + h) * Lc + l) * Kc + kk) = res;
            }
        }
    }
}

// ---------------- causal attention: tf32 MMA flash (no-max softmax) -----------
// Block: 128 queries (8 warps x 16 rows), 64-key tiles.
// S = Q@K^T via m16n8k8 (A=Q rows, B=K rows, dims padded to 16 with zeros).
// Softmax on fragments; P staged via warp-private smem slice; PV via m16n8k8
// (A=P from smem, B=V transposed [dim][key], dims padded to 16 with zeros).
#define SK_S 20
#define SV_S 68
#define SP_S 68

__global__ __launch_bounds__(256)
void attn_kernel()
{
    __shared__ float sK[64][SK_S];      // [key][dim0..15] tf32 (12..15 zero)
    __shared__ float sVt[16][SV_S];     // [dim0..15][key] tf32 (rows 12..15 zero)
    __shared__ float sP[8][16][SP_S];   // per-warp P slice [qrow][key] tf32

    const int qt   = gridDim.x - 1 - blockIdx.x;   // heavy tiles first
    const int h    = blockIdx.y, bb = blockIdx.z;
    const int tid  = threadIdx.x;
    const int w    = tid >> 5;
    const int lane = tid & 31;
    const int grp  = lane >> 2;
    const int tig  = lane & 3;

    size_t head = ((size_t)bb * Hc + h) * Lc * Kc;
    const float* qp = g_q + head;
    const float* kp = g_k + head;
    const float* vp = g_v + head;

    // zero pad regions (written once; first-tile __syncthreads publishes)
    sK[tid >> 2][12 + (tid & 3)] = 0.f;             // 256 threads = 64x4
    sVt[12 + (tid >> 6)][tid & 63] = 0.f;           // 256 threads = 4x64

    const int qbase = qt * 128;
    const int l0 = qbase + w * 16 + grp;
    const int l8 = l0 + 8;
    const float scale = 0.4164682333693345f;        // log2(e)/sqrt(12)

    // Q fragments (2 k-chunks), scaled, tf32
    uint32_t qa[2][4];
    qa[0][0] = tf32b(qp[(size_t)l0 * 12 + tig] * scale);
    qa[0][1] = tf32b(qp[(size_t)l8 * 12 + tig] * scale);
    qa[0][2] = tf32b(qp[(size_t)l0 * 12 + tig + 4] * scale);
    qa[0][3] = tf32b(qp[(size_t)l8 * 12 + tig + 4] * scale);
    qa[1][0] = tf32b(qp[(size_t)l0 * 12 + tig + 8] * scale);
    qa[1][1] = tf32b(qp[(size_t)l8 * 12 + tig + 8] * scale);
    qa[1][2] = 0u;
    qa[1][3] = 0u;

    float oc[2][4];
#pragma unroll
    for (int i = 0; i < 2; i++)
#pragma unroll
        for (int j = 0; j < 4; j++) oc[i][j] = 0.f;
    float dsum0 = 0.f, dsum1 = 0.f;

    const int qloc0 = w * 16 + grp;
    const int qloc1 = qloc0 + 8;
    const int ntile = 2 * qt + 2;

    for (int kt = 0; kt < ntile; kt++) {
        __syncthreads();
        // stage K, V(transposed) tiles, tf32
        {
            int i = tid;                            // 192 active
            if (i < 192) {
                int key = i / 3, c4 = (i % 3) * 4;
                const float* ksrc = kp + (size_t)(kt * 64 + key) * 12 + c4;
                float4 kv = *(const float4*)ksrc;
                sK[key][c4+0] = to_tf32(kv.x); sK[key][c4+1] = to_tf32(kv.y);
                sK[key][c4+2] = to_tf32(kv.z); sK[key][c4+3] = to_tf32(kv.w);
                const float* vsrc = vp + (size_t)(kt * 64 + key) * 12 + c4;
                float4 vv = *(const float4*)vsrc;
                sVt[c4+0][key] = to_tf32(vv.x); sVt[c4+1][key] = to_tf32(vv.y);
                sVt[c4+2][key] = to_tf32(vv.z); sVt[c4+3][key] = to_tf32(vv.w);
            }
        }
        __syncthreads();

        // scores: c[nt] = Q(16 rows) @ K^T(8 keys per nt)
        float c[8][4];
#pragma unroll
        for (int nt = 0; nt < 8; nt++) {
            c[nt][0] = 0.f; c[nt][1] = 0.f; c[nt][2] = 0.f; c[nt][3] = 0.f;
        }
#pragma unroll
        for (int nt = 0; nt < 8; nt++) {
#pragma unroll
            for (int kc = 0; kc < 2; kc++) {
                uint32_t b0 = __float_as_uint(sK[nt * 8 + grp][kc * 8 + tig]);
                uint32_t b1 = __float_as_uint(sK[nt * 8 + grp][kc * 8 + tig + 4]);
                mma_tf32(c[nt], qa[kc], b0, b1);
            }
        }

        // softmax (no-max): p = 2^s, causal mask on diagonal tiles
        const bool masked = (kt >= 2 * qt);
        const int koff = (kt - 2 * qt) * 64;
#pragma unroll
        for (int nt = 0; nt < 8; nt++) {
            int kl = nt * 8 + 2 * tig;
            float p0 = ex2(c[nt][0]);
            float p1 = ex2(c[nt][1]);
            float p2 = ex2(c[nt][2]);
            float p3 = ex2(c[nt][3]);
            if (masked) {
                if (koff + kl     > qloc0) p0 = 0.f;
                if (koff + kl + 1 > qloc0) p1 = 0.f;
                if (koff + kl     > qloc1) p2 = 0.f;
                if (koff + kl + 1 > qloc1) p3 = 0.f;
            }
            dsum0 += p0 + p1;
            dsum1 += p2 + p3;
            float2 lo = make_float2(to_tf32(p0), to_tf32(p1));
            float2 hi = make_float2(to_tf32(p2), to_tf32(p3));
            *(float2*)&sP[w][grp]    [kl] = lo;
            *(float2*)&sP[w][grp + 8][kl] = hi;
        }
        __syncwarp();

        // PV: oc += P(16 rows x 64 keys) @ V(64 keys x 16 dims)
#pragma unroll
        for (int kc = 0; kc < 8; kc++) {
            uint32_t a[4];
            a[0] = __float_as_uint(sP[w][grp]    [kc * 8 + tig]);
            a[1] = __float_as_uint(sP[w][grp + 8][kc * 8 + tig]);
            a[2] = __float_as_uint(sP[w][grp]    [kc * 8 + tig + 4]);
            a[3] = __float_as_uint(sP[w][grp + 8][kc * 8 + tig + 4]);
#pragma unroll
            for (int nt2 = 0; nt2 < 2; nt2++) {
                uint32_t b0 = __float_as_uint(sVt[nt2 * 8 + grp][kc * 8 + tig]);
                uint32_t b1 = __float_as_uint(sVt[nt2 * 8 + grp][kc * 8 + tig + 4]);
                mma_tf32(oc[nt2], a, b0, b1);
            }
        }
    }

    // reduce row sums across the 4 tig lanes (same grp)
    dsum0 += __shfl_xor_sync(0xffffffffu, dsum0, 1);
    dsum0 += __shfl_xor_sync(0xffffffffu, dsum0, 2);
    dsum1 += __shfl_xor_sync(0xffffffffu, dsum1, 1);
    dsum1 += __shfl_xor_sync(0xffffffffu, dsum1, 2);
    float i0 = 1.f / dsum0, i1 = 1.f / dsum1;

    float* o0 = g_ctx + (((size_t)bb * Lc + l0) * Hc + h) * Kc;
    float* o1 = g_ctx + (((size_t)bb * Lc + l8) * Hc + h) * Kc;
    *(float2*)(o0 + 2 * tig) = make_float2(oc[0][0] * i0, oc[0][1] * i0);
    *(float2*)(o1 + 2 * tig) = make_float2(oc[0][2] * i1, oc[0][3] * i1);
    if (tig < 2) {
        *(float2*)(o0 + 8 + 2 * tig) = make_float2(oc[1][0] * i0, oc[1][1] * i0);
        *(float2*)(o1 + 8 + 2 * tig) = make_float2(oc[1][2] * i1, oc[1][3] * i1);
    }
}

// ---------------- output projection + residual + fused LN2: tf32 MMA ----------
#define PA_S 52
#define PB_S 200
#define PA_FLOATS (64 * PA_S)
#define PB_FLOATS (48 * PB_S)
#define PST_S 196
#define PROJ_SMEM_BYTES ((PA_FLOATS + PB_FLOATS) * 4)   // 12928 floats > 64*196

__global__ __launch_bounds__(256, 4)
void proj_mma_kernel(const float* __restrict__ x,
                     const float* __restrict__ wo,
                     const float* __restrict__ bo,
                     const float* __restrict__ ln_g,
                     const float* __restrict__ ln_b)
{
    extern __shared__ float smem[];
    float* sA = smem;                 // [64][52]  ctx rows, tf32
    float* sB = smem + PA_FLOATS;     // [48][200] wo, tf32

    const int tid  = threadIdx.x;
    const int w    = tid >> 5;
    const int lane = tid & 31;
    const int tig  = lane & 3;
    const int grp  = lane >> 2;
    const int rowbase = blockIdx.x * 64;

    for (int idx = tid; idx < 64 * 12; idx += 256) {
        int r = idx / 12, c4 = (idx % 12) * 4;
        float4 v = *(const float4*)(g_ctx + (size_t)(rowbase + r) * 48 + c4);
        float* d = sA + r * PA_S + c4;
        d[0] = to_tf32(v.x); d[1] = to_tf32(v.y);
        d[2] = to_tf32(v.z); d[3] = to_tf32(v.w);
    }
    for (int idx = tid; idx < 48 * 48; idx += 256) {
        int r = idx / 48, c4 = (idx % 48) * 4;
        float4 v = *(const float4*)(wo + (size_t)r * Dc + c4);
        float* d = sB + r * PB_S + c4;
        d[0] = to_tf32(v.x); d[1] = to_tf32(v.y);
        d[2] = to_tf32(v.z); d[3] = to_tf32(v.w);
    }
    __syncthreads();

    const int mbase = (w & 1) * 32;
    const int nbase = (w >> 1) * 48;
    float c[2][6][4];
#pragma unroll
    for (int i = 0; i < 2; i++)
#pragma unroll
        for (int j = 0; j < 6; j++)
#pragma unroll
            for (int q = 0; q < 4; q++) c[i][j][q] = 0.f;

#pragma unroll
    for (int ks = 0; ks < 6; ks++) {
        const int c0 = ks * 8;
        uint32_t a[2][4];
#pragma unroll
        for (int mt = 0; mt < 2; mt++) {
            const float* ap = sA + (mbase + mt * 16 + grp) * PA_S + c0 + tig;
            a[mt][0] = __float_as_uint(ap[0]);
            a[mt][1] = __float_as_uint(ap[8 * PA_S]);
            a[mt][2] = __float_as_uint(ap[4]);
            a[mt][3] = __float_as_uint(ap[8 * PA_S + 4]);
        }
        const float* bp = sB + (c0 + tig) * PB_S + nbase + grp;
#pragma unroll
        for (int nt = 0; nt < 6; nt++) {
            uint32_t b0 = __float_as_uint(bp[nt * 8]);
            uint32_t b1 = __float_as_uint(bp[nt * 8 + 4 * PB_S]);
            mma_tf32(c[0][nt], a[0], b0, b1);
            mma_tf32(c[1][nt], a[1], b0, b1);
        }
    }
    __syncthreads();                       // done with sA/sB; reuse as stage

    float* stage = smem;                   // [64][196]
#pragma unroll
    for (int mt = 0; mt < 2; mt++) {
#pragma unroll
        for (int rs = 0; rs < 2; rs++) {
            int r = mbase + mt * 16 + grp + rs * 8;
            size_t off = (size_t)(rowbase + r) * Dc;
#pragma unroll
            for (int nt = 0; nt < 6; nt++) {
                int n = nbase + nt * 8 + tig * 2;
                float2 xv = *(const float2*)(x + off + n);
                float2 res;
                res.x = c[mt][nt][rs * 2 + 0] + bo[n]     + xv.x;
                res.y = c[mt][nt][rs * 2 + 1] + bo[n + 1] + xv.y;
                *(float2*)(g_y1 + off + n) = res;
                *(float2*)(stage + r * PST_S + n) = res;
            }
        }
    }
    __syncthreads();

    // fused LN2: warp w handles rows w, w+8, ... -> g_xn (fp32)
    for (int r = w; r < 64; r += 8) {
        float vv[6]; float s = 0.f;
#pragma unroll
        for (int i = 0; i < 6; i++) { vv[i] = stage[r * PST_S + lane + 32*i]; s += vv[i]; }
#pragma unroll
        for (int o = 16; o; o >>= 1) s += __shfl_xor_sync(0xffffffffu, s, o);
        float mean = s * (1.f/192.f);
        float vs = 0.f;
#pragma unroll
        for (int i = 0; i < 6; i++) { float dd = vv[i] - mean; vs += dd*dd; }
#pragma unroll
        for (int o = 16; o; o >>= 1) vs += __shfl_xor_sync(0xffffffffu, vs, o);
        float inv = rsqrtf(vs * (1.f/192.f) + 1e-3f);
#pragma unroll
        for (int i = 0; i < 6; i++) {
            int cc = lane + 32*i;
            g_xn[(size_t)(rowbase + r) * Dc + cc] =
                (vv[i] - mean) * inv * ln_g[cc] + ln_b[cc];
        }
    }
}

// ---------------- conv1d as tf32 tensor-core GEMM ----------------
#define SA_STRIDE 196
#define SB_STRIDE 200
#define SA_FLOATS (66 * SA_STRIDE)
#define SB_FLOATS (32 * SB_STRIDE)
#define CONV_SMEM_BYTES ((SA_FLOATS + 2 * SB_FLOATS) * 4)

template<int MODE>
__global__ __launch_bounds__(256, 2)
void conv_mma_kernel(const float* __restrict__ W,
                     const float* __restrict__ bias,
                     float* __restrict__ out)
{
    extern __shared__ float smem[];
    float* sA = smem;                    // [66][196]
    float* sB = smem + SA_FLOATS;        // [2][32][200]

    const int tid  = threadIdx.x;
    const int w    = tid >> 5;
    const int lane = tid & 31;
    const int tig  = lane & 3;
    const int grp  = lane >> 2;
    const int l0   = blockIdx.x * 64;
    const int bb   = blockIdx.y;
    const float* srcb = ((MODE == 0) ? g_xn : g_h) + (size_t)bb * Lc * Dc;

    for (int idx = tid; idx < 66 * 48; idx += 256) {
        int r = idx / 48, c4 = (idx % 48) * 4;
        int l = l0 - 1 + r; l = l < 0 ? 0 : (l > Lc - 1 ? Lc - 1 : l);
        float4 v = *(const float4*)(srcb + (size_t)l * Dc + c4);
        float* d = sA + r * SA_STRIDE + c4;
        d[0] = to_tf32(v.x); d[1] = to_tf32(v.y);
        d[2] = to_tf32(v.z); d[3] = to_tf32(v.w);
    }

    const int mbase = (w & 1) * 32;
    const int nbase = (w >> 1) * 48;
    float c[2][6][4];
#pragma unroll
    for (int i = 0; i < 2; i++)
#pragma unroll
        for (int j = 0; j < 6; j++)
#pragma unroll
            for (int q = 0; q < 4; q++) c[i][j][q] = 0.f;

    auto loadW = [&](int kc, int bf) {
        float* dstb = sB + bf * SB_FLOATS;
#pragma unroll
        for (int it = 0; it < 6; it++) {
            int idx = tid + it * 256;
            int k = idx / 48, c4 = (idx % 48) * 4;
            float4 v = *(const float4*)(W + ((size_t)(kc * 32 + k)) * Dc + c4);
            float* d = dstb + k * SB_STRIDE + c4;
            d[0] = to_tf32(v.x); d[1] = to_tf32(v.y);
            d[2] = to_tf32(v.z); d[3] = to_tf32(v.w);
        }
    };

    loadW(0, 0);
    __syncthreads();

    int buf = 0;
    for (int kc = 0; kc < 18; kc++) {
        if (kc < 17) loadW(kc + 1, buf ^ 1);
        const int t  = kc / 6;
        const int cc = (kc % 6) * 32;
        const float* bBuf = sB + buf * SB_FLOATS;
#pragma unroll
        for (int ks = 0; ks < 4; ks++) {
            const int c0 = cc + ks * 8;
            uint32_t a[2][4];
#pragma unroll
            for (int mt = 0; mt < 2; mt++) {
                const float* ap = sA + (mbase + mt * 16 + grp + t) * SA_STRIDE + c0 + tig;
                a[mt][0] = __float_as_uint(ap[0]);
                a[mt][1] = __float_as_uint(ap[8 * SA_STRIDE]);
                a[mt][2] = __float_as_uint(ap[4]);
                a[mt][3] = __float_as_uint(ap[8 * SA_STRIDE + 4]);
            }
            const float* bp = bBuf + (ks * 8 + tig) * SB_STRIDE + nbase + grp;
#pragma unroll
            for (int nt = 0; nt < 6; nt++) {
                uint32_t b0 = __float_as_uint(bp[nt * 8]);
                uint32_t b1 = __float_as_uint(bp[nt * 8 + 4 * SB_STRIDE]);
                mma_tf32(c[0][nt], a[0], b0, b1);
                mma_tf32(c[1][nt], a[1], b0, b1);
            }
        }
        __syncthreads();
        buf ^= 1;
    }

    float* dst = (MODE == 0) ? g_h : out;
#pragma unroll
    for (int mt = 0; mt < 2; mt++) {
#pragma unroll
        for (int rs = 0; rs < 2; rs++) {
            int l = l0 + mbase + mt * 16 + grp + rs * 8;
            bool interior = (l >= 1) && (l <= Lc - 2);
            size_t rowoff = ((size_t)bb * Lc + l) * Dc;
#pragma unroll
            for (int nt = 0; nt < 6; nt++) {
                int n = nbase + nt * 8 + tig * 2;
                float v0 = c[mt][nt][rs * 2 + 0] + bias[n];
                float v1 = c[mt][nt][rs * 2 + 1] + bias[n + 1];
                float2 res;
                if (MODE == 0) {
                    res.x = interior ? fmaxf(v0, 0.f) : 0.f;
                    res.y = interior ? fmaxf(v1, 0.f) : 0.f;
                } else {
                    float2 y = *(const float2*)(g_y1 + rowoff + n);
                    res.x = y.x + (interior ? v0 : 0.f);
                    res.y = y.y + (interior ? v1 : 0.f);
                }
                *(float2*)(dst + rowoff + n) = res;
            }
        }
    }
}

// ---------------- launcher ----------------
extern "C" void kernel_launch(void* const* d_in, const int* in_sizes, int n_in,
                              void* d_out, int out_size)
{
    const float* x     = (const float*)d_in[0];
    const float* ln1_g = (const float*)d_in[1];
    const float* ln1_b = (const float*)d_in[2];
    const float* wq    = (const float*)d_in[3];
    const float* bq    = (const float*)d_in[4];
    const float* wk    = (const float*)d_in[5];
    const float* bk    = (const float*)d_in[6];
    const float* wv    = (const float*)d_in[7];
    const float* bv    = (const float*)d_in[8];
    const float* wo    = (const float*)d_in[9];
    const float* bo    = (const float*)d_in[10];
    const float* ln2_g = (const float*)d_in[11];
    const float* ln2_b = (const float*)d_in[12];
    const float* c1_w  = (const float*)d_in[13];
    const float* c1_b  = (const float*)d_in[14];
    const float* c2_w  = (const float*)d_in[15];
    const float* c2_b  = (const float*)d_in[16];
    float* outp = (float*)d_out;

    cudaFuncSetAttribute(conv_mma_kernel<0>,
                         cudaFuncAttributeMaxDynamicSharedMemorySize, CONV_SMEM_BYTES);
    cudaFuncSetAttribute(conv_mma_kernel<1>,
                         cudaFuncAttributeMaxDynamicSharedMemorySize, CONV_SMEM_BYTES);
    cudaFuncSetAttribute(qkv_mma_kernel,
                         cudaFuncAttributeMaxDynamicSharedMemorySize, QKV_SMEM_BYTES);
    cudaFuncSetAttribute(proj_mma_kernel,
                         cudaFuncAttributeMaxDynamicSharedMemorySize, PROJ_SMEM_BYTES);

    qkv_mma_kernel<<<(Bc*Lc)/64, 192, QKV_SMEM_BYTES>>>(x, ln1_g, ln1_b,
                                                        wq, bq, wk, bk, wv, bv);
    attn_kernel<<<dim3(Lc/128, Hc, Bc), 256>>>();
    proj_mma_kernel<<<(Bc*Lc)/64, 256, PROJ_SMEM_BYTES>>>(x, wo, bo, ln2_g, ln2_b);
    conv_mma_kernel<0><<<dim3(Lc/64, Bc), 256, CONV_SMEM_BYTES>>>(c1_w, c1_b, outp);
    conv_mma_kernel<1><<<dim3(Lc/64, Bc), 256, CONV_SMEM_BYTES>>>(c2_w, c2_b, outp);
}

// round 15
// speedup vs baseline: 2.4608x; 1.0082x over previous
#include <cuda_runtime.h>
#include <math.h>
#include <stdint.h>

#define Bc 16
#define Lc 2048
#define Dc 192
#define Hc 4
#define Kc 12

// ---------------- scratch (no allocations allowed) ----------------
__device__ float g_xn [(size_t)Bc*Lc*Dc];       // xn2 (written by fused proj+LN2)
__device__ float g_q  [(size_t)Bc*Hc*Lc*Kc];    // [B,H,L,K]
__device__ float g_k  [(size_t)Bc*Hc*Lc*Kc];
__device__ float g_v  [(size_t)Bc*Hc*Lc*Kc];
__device__ float g_ctx[(size_t)Bc*Lc*Hc*Kc];    // [B,L,H,K]
__device__ float g_y1 [(size_t)Bc*Lc*Dc];       // x + MHA
__device__ float g_h  [(size_t)Bc*Lc*Dc];       // relu(conv1), zero rows 0, L-1

__device__ __forceinline__ float ex2(float x) {
    float y; asm("ex2.approx.f32 %0, %1;" : "=f"(y) : "f"(x)); return y;
}
__device__ __forceinline__ float to_tf32(float x) {
    uint32_t u; asm("cvt.rna.tf32.f32 %0, %1;" : "=r"(u) : "f"(x));
    return __uint_as_float(u);
}
__device__ __forceinline__ uint32_t tf32b(float x) {
    uint32_t u; asm("cvt.rna.tf32.f32 %0, %1;" : "=r"(u) : "f"(x));
    return u;
}
// RNA-round a float4 in registers, then one STS.128 at the call site.
__device__ __forceinline__ float4 tf32x4(float4 v) {
    return make_float4(to_tf32(v.x), to_tf32(v.y), to_tf32(v.z), to_tf32(v.w));
}
__device__ __forceinline__ void mma_tf32(float* c, const uint32_t* a,
                                         uint32_t b0, uint32_t b1)
{
    asm volatile(
        "mma.sync.aligned.m16n8k8.row.col.f32.tf32.tf32.f32 "
        "{%0,%1,%2,%3}, {%4,%5,%6,%7}, {%8,%9}, {%0,%1,%2,%3};"
        : "+f"(c[0]), "+f"(c[1]), "+f"(c[2]), "+f"(c[3])
        : "r"(a[0]), "r"(a[1]), "r"(a[2]), "r"(a[3]), "r"(b0), "r"(b1));
}

// ---------------- QKV projection + fused LN1: tf32 MMA ----------------
// M=64/block, N=3x48, K=192. 192 threads = 6 warps.
#define QA_S 196
#define QB_S 152
#define QA_FLOATS (64 * QA_S)
#define QB_FLOATS (32 * QB_S)
#define QKV_SMEM_BYTES ((QA_FLOATS + 2 * QB_FLOATS) * 4)

__global__ __launch_bounds__(192, 2)
void qkv_mma_kernel(const float* __restrict__ x,
                    const float* __restrict__ ln_g, const float* __restrict__ ln_b,
                    const float* __restrict__ wq, const float* __restrict__ bq,
                    const float* __restrict__ wk, const float* __restrict__ bk,
                    const float* __restrict__ wv, const float* __restrict__ bv)
{
    extern __shared__ float smem[];
    float* sA = smem;                 // [64][196] raw x rows -> LN'd tf32 in-place
    float* sB = smem + QA_FLOATS;     // [2][32][152] tf32 weights (q|k|v cols)

    const int tid  = threadIdx.x;
    const int w    = tid >> 5;
    const int lane = tid & 31;
    const int tig  = lane & 3;
    const int grp  = lane >> 2;
    const int rowbase = blockIdx.x * 64;
    const int bb   = rowbase / Lc;
    const int lloc = rowbase % Lc;

    auto loadW = [&](int kc, int bf) {
        float* dstb = sB + bf * QB_FLOATS;
#pragma unroll
        for (int it = 0; it < 6; it++) {
            int idx = tid + it * 192;            // 32*36 float4 = 1152
            int k = idx / 36, c = (idx % 36) * 4;
            int m = c / 48, lc = c % 48;
            const float* src = (m == 0) ? wq : (m == 1) ? wk : wv;
            float4 v = *(const float4*)(src + (size_t)(kc * 32 + k) * 48 + lc);
            *(float4*)(dstb + k * QB_S + c) = tf32x4(v);
        }
    };

    for (int idx = tid; idx < 64 * 48; idx += 192) {
        int r = idx / 48, c4 = (idx % 48) * 4;
        *(float4*)(sA + r * QA_S + c4) =
            *(const float4*)(x + (size_t)(rowbase + r) * Dc + c4);
    }
    loadW(0, 0);
    __syncthreads();

    // fused LN1: warp w handles rows w, w+6, ...
    for (int r = w; r < 64; r += 6) {
        float vv[6]; float s = 0.f;
#pragma unroll
        for (int i = 0; i < 6; i++) { vv[i] = sA[r * QA_S + lane + 32*i]; s += vv[i]; }
#pragma unroll
        for (int o = 16; o; o >>= 1) s += __shfl_xor_sync(0xffffffffu, s, o);
        float mean = s * (1.f/192.f);
        float vs = 0.f;
#pragma unroll
        for (int i = 0; i < 6; i++) { float dd = vv[i] - mean; vs += dd*dd; }
#pragma unroll
        for (int o = 16; o; o >>= 1) vs += __shfl_xor_sync(0xffffffffu, vs, o);
        float inv = rsqrtf(vs * (1.f/192.f) + 1e-3f);
#pragma unroll
        for (int i = 0; i < 6; i++) {
            int c = lane + 32*i;
            sA[r * QA_S + c] = to_tf32((vv[i] - mean) * inv * ln_g[c] + ln_b[c]);
        }
    }
    __syncthreads();

    const int s     = w >> 1;
    const int mbase = (w & 1) * 32;
    float c[2][6][4];
#pragma unroll
    for (int i = 0; i < 2; i++)
#pragma unroll
        for (int j = 0; j < 6; j++)
#pragma unroll
            for (int q = 0; q < 4; q++) c[i][j][q] = 0.f;

    int buf = 0;
    for (int kc = 0; kc < 6; kc++) {
        if (kc < 5) loadW(kc + 1, buf ^ 1);
        const float* bBuf = sB + buf * QB_FLOATS + s * 48;
#pragma unroll
        for (int ks = 0; ks < 4; ks++) {
            const int c0 = kc * 32 + ks * 8;
            uint32_t a[2][4];
#pragma unroll
            for (int mt = 0; mt < 2; mt++) {
                const float* ap = sA + (mbase + mt * 16 + grp) * QA_S + c0 + tig;
                a[mt][0] = __float_as_uint(ap[0]);
                a[mt][1] = __float_as_uint(ap[8 * QA_S]);
                a[mt][2] = __float_as_uint(ap[4]);
                a[mt][3] = __float_as_uint(ap[8 * QA_S + 4]);
            }
            const float* bp = bBuf + (ks * 8 + tig) * QB_S + grp;
#pragma unroll
            for (int nt = 0; nt < 6; nt++) {
                uint32_t b0 = __float_as_uint(bp[nt * 8]);
                uint32_t b1 = __float_as_uint(bp[nt * 8 + 4 * QB_S]);
                mma_tf32(c[0][nt], a[0], b0, b1);
                mma_tf32(c[1][nt], a[1], b0, b1);
            }
        }
        __syncthreads();
        buf ^= 1;
    }

    const float* Bp = (s == 0) ? bq : (s == 1) ? bk : bv;
    float* O = (s == 0) ? g_q : (s == 1) ? g_k : g_v;
#pragma unroll
    for (int mt = 0; mt < 2; mt++) {
#pragma unroll
        for (int rs = 0; rs < 2; rs++) {
            int l = lloc + mbase + mt * 16 + grp + rs * 8;
#pragma unroll
            for (int nt = 0; nt < 6; nt++) {
                int n = nt * 8 + tig * 2;       // 0..47, even
                int h = n / 12, kk = n % 12;
                float2 res;
                res.x = c[mt][nt][rs * 2 + 0] + Bp[n];
                res.y = c[mt][nt][rs * 2 + 1] + Bp[n + 1];
                *(float2*)(O + (((size_t)bb * Hc + h) * Lc + l) * Kc + kk) = res;
            }
        }
    }
}

// ---------------- causal attention: tf32 MMA flash (no-max softmax) -----------
// Block: 128 queries (8 warps x 16 rows), 64-key tiles.
#define SK_S 20
#define SV_S 68
#define SP_S 68

__global__ __launch_bounds__(256)
void attn_kernel()
{
    __shared__ float sK[64][SK_S];      // [key][dim0..15] tf32 (12..15 zero)
    __shared__ float sVt[16][SV_S];     // [dim0..15][key] tf32 (rows 12..15 zero)
    __shared__ float sP[8][16][SP_S];   // per-warp P slice [qrow][key] tf32

    const int qt   = gridDim.x - 1 - blockIdx.x;   // heavy tiles first
    const int h    = blockIdx.y, bb = blockIdx.z;
    const int tid  = threadIdx.x;
    const int w    = tid >> 5;
    const int lane = tid & 31;
    const int grp  = lane >> 2;
    const int tig  = lane & 3;

    size_t head = ((size_t)bb * Hc + h) * Lc * Kc;
    const float* qp = g_q + head;
    const float* kp = g_k + head;
    const float* vp = g_v + head;

    // zero pad regions (written once; first-tile __syncthreads publishes)
    sK[tid >> 2][12 + (tid & 3)] = 0.f;             // 256 threads = 64x4
    sVt[12 + (tid >> 6)][tid & 63] = 0.f;           // 256 threads = 4x64

    const int qbase = qt * 128;
    const int l0 = qbase + w * 16 + grp;
    const int l8 = l0 + 8;
    const float scale = 0.4164682333693345f;        // log2(e)/sqrt(12)

    // Q fragments (2 k-chunks), scaled, tf32 (RNA)
    uint32_t qa[2][4];
    qa[0][0] = tf32b(qp[(size_t)l0 * 12 + tig] * scale);
    qa[0][1] = tf32b(qp[(size_t)l8 * 12 + tig] * scale);
    qa[0][2] = tf32b(qp[(size_t)l0 * 12 + tig + 4] * scale);
    qa[0][3] = tf32b(qp[(size_t)l8 * 12 + tig + 4] * scale);
    qa[1][0] = tf32b(qp[(size_t)l0 * 12 + tig + 8] * scale);
    qa[1][1] = tf32b(qp[(size_t)l8 * 12 + tig + 8] * scale);
    qa[1][2] = 0u;
    qa[1][3] = 0u;

    float oc[2][4];
#pragma unroll
    for (int i = 0; i < 2; i++)
#pragma unroll
        for (int j = 0; j < 4; j++) oc[i][j] = 0.f;
    float dsum0 = 0.f, dsum1 = 0.f;

    const int qloc0 = w * 16 + grp;
    const int qloc1 = qloc0 + 8;
    const int ntile = 2 * qt + 2;

    for (int kt = 0; kt < ntile; kt++) {
        __syncthreads();
        // stage K (cvt in regs -> STS.128) and V transposed (scalar cvt)
        {
            int i = tid;                            // 192 active
            if (i < 192) {
                int key = i / 3, c4 = (i % 3) * 4;
                float4 kv = *(const float4*)(kp + (size_t)(kt * 64 + key) * 12 + c4);
                *(float4*)&sK[key][c4] = tf32x4(kv);
                float4 vv = *(const float4*)(vp + (size_t)(kt * 64 + key) * 12 + c4);
                sVt[c4+0][key] = to_tf32(vv.x); sVt[c4+1][key] = to_tf32(vv.y);
                sVt[c4+2][key] = to_tf32(vv.z); sVt[c4+3][key] = to_tf32(vv.w);
            }
        }
        __syncthreads();

        // scores: c[nt] = Q(16 rows) @ K^T(8 keys per nt)
        float c[8][4];
#pragma unroll
        for (int nt = 0; nt < 8; nt++) {
            c[nt][0] = 0.f; c[nt][1] = 0.f; c[nt][2] = 0.f; c[nt][3] = 0.f;
        }
#pragma unroll
        for (int nt = 0; nt < 8; nt++) {
#pragma unroll
            for (int kc = 0; kc < 2; kc++) {
                uint32_t b0 = __float_as_uint(sK[nt * 8 + grp][kc * 8 + tig]);
                uint32_t b1 = __float_as_uint(sK[nt * 8 + grp][kc * 8 + tig + 4]);
                mma_tf32(c[nt], qa[kc], b0, b1);
            }
        }

        // softmax (no-max): p = 2^s, causal mask on diagonal tiles
        const bool masked = (kt >= 2 * qt);
        const int koff = (kt - 2 * qt) * 64;
#pragma unroll
        for (int nt = 0; nt < 8; nt++) {
            int kl = nt * 8 + 2 * tig;
            float p0 = ex2(c[nt][0]);
            float p1 = ex2(c[nt][1]);
            float p2 = ex2(c[nt][2]);
            float p3 = ex2(c[nt][3]);
            if (masked) {
                if (koff + kl     > qloc0) p0 = 0.f;
                if (koff + kl + 1 > qloc0) p1 = 0.f;
                if (koff + kl     > qloc1) p2 = 0.f;
                if (koff + kl + 1 > qloc1) p3 = 0.f;
            }
            dsum0 += p0 + p1;
            dsum1 += p2 + p3;
            float2 lo = make_float2(to_tf32(p0), to_tf32(p1));
            float2 hi = make_float2(to_tf32(p2), to_tf32(p3));
            *(float2*)&sP[w][grp]    [kl] = lo;
            *(float2*)&sP[w][grp + 8][kl] = hi;
        }
        __syncwarp();

        // PV: oc += P(16 rows x 64 keys) @ V(64 keys x 16 dims)
#pragma unroll
        for (int kc = 0; kc < 8; kc++) {
            uint32_t a[4];
            a[0] = __float_as_uint(sP[w][grp]    [kc * 8 + tig]);
            a[1] = __float_as_uint(sP[w][grp + 8][kc * 8 + tig]);
            a[2] = __float_as_uint(sP[w][grp]    [kc * 8 + tig + 4]);
            a[3] = __float_as_uint(sP[w][grp + 8][kc * 8 + tig + 4]);
#pragma unroll
            for (int nt2 = 0; nt2 < 2; nt2++) {
                uint32_t b0 = __float_as_uint(sVt[nt2 * 8 + grp][kc * 8 + tig]);
                uint32_t b1 = __float_as_uint(sVt[nt2 * 8 + grp][kc * 8 + tig + 4]);
                mma_tf32(oc[nt2], a, b0, b1);
            }
        }
    }

    // reduce row sums across the 4 tig lanes (same grp)
    dsum0 += __shfl_xor_sync(0xffffffffu, dsum0, 1);
    dsum0 += __shfl_xor_sync(0xffffffffu, dsum0, 2);
    dsum1 += __shfl_xor_sync(0xffffffffu, dsum1, 1);
    dsum1 += __shfl_xor_sync(0xffffffffu, dsum1, 2);
    float i0 = 1.f / dsum0, i1 = 1.f / dsum1;

    float* o0 = g_ctx + (((size_t)bb * Lc + l0) * Hc + h) * Kc;
    float* o1 = g_ctx + (((size_t)bb * Lc + l8) * Hc + h) * Kc;
    *(float2*)(o0 + 2 * tig) = make_float2(oc[0][0] * i0, oc[0][1] * i0);
    *(float2*)(o1 + 2 * tig) = make_float2(oc[0][2] * i1, oc[0][3] * i1);
    if (tig < 2) {
        *(float2*)(o0 + 8 + 2 * tig) = make_float2(oc[1][0] * i0, oc[1][1] * i0);
        *(float2*)(o1 + 8 + 2 * tig) = make_float2(oc[1][2] * i1, oc[1][3] * i1);
    }
}

// ---------------- output projection + residual + fused LN2: tf32 MMA ----------
#define PA_S 52
#define PB_S 200
#define PA_FLOATS (64 * PA_S)
#define PB_FLOATS (48 * PB_S)
#define PST_S 196
#define PROJ_SMEM_BYTES ((PA_FLOATS + PB_FLOATS) * 4)   // 12928 floats > 64*196

__global__ __launch_bounds__(256, 4)
void proj_mma_kernel(const float* __restrict__ x,
                     const float* __restrict__ wo,
                     const float* __restrict__ bo,
                     const float* __restrict__ ln_g,
                     const float* __restrict__ ln_b)
{
    extern __shared__ float smem[];
    float* sA = smem;                 // [64][52]  ctx rows, tf32
    float* sB = smem + PA_FLOATS;     // [48][200] wo, tf32

    const int tid  = threadIdx.x;
    const int w    = tid >> 5;
    const int lane = tid & 31;
    const int tig  = lane & 3;
    const int grp  = lane >> 2;
    const int rowbase = blockIdx.x * 64;

    for (int idx = tid; idx < 64 * 12; idx += 256) {
        int r = idx / 12, c4 = (idx % 12) * 4;
        float4 v = *(const float4*)(g_ctx + (size_t)(rowbase + r) * 48 + c4);
        *(float4*)(sA + r * PA_S + c4) = tf32x4(v);
    }
    for (int idx = tid; idx < 48 * 48; idx += 256) {
        int r = idx / 48, c4 = (idx % 48) * 4;
        float4 v = *(const float4*)(wo + (size_t)r * Dc + c4);
        *(float4*)(sB + r * PB_S + c4) = tf32x4(v);
    }
    __syncthreads();

    const int mbase = (w & 1) * 32;
    const int nbase = (w >> 1) * 48;
    float c[2][6][4];
#pragma unroll
    for (int i = 0; i < 2; i++)
#pragma unroll
        for (int j = 0; j < 6; j++)
#pragma unroll
            for (int q = 0; q < 4; q++) c[i][j][q] = 0.f;

#pragma unroll
    for (int ks = 0; ks < 6; ks++) {
        const int c0 = ks * 8;
        uint32_t a[2][4];
#pragma unroll
        for (int mt = 0; mt < 2; mt++) {
            const float* ap = sA + (mbase + mt * 16 + grp) * PA_S + c0 + tig;
            a[mt][0] = __float_as_uint(ap[0]);
            a[mt][1] = __float_as_uint(ap[8 * PA_S]);
            a[mt][2] = __float_as_uint(ap[4]);
            a[mt][3] = __float_as_uint(ap[8 * PA_S + 4]);
        }
        const float* bp = sB + (c0 + tig) * PB_S + nbase + grp;
#pragma unroll
        for (int nt = 0; nt < 6; nt++) {
            uint32_t b0 = __float_as_uint(bp[nt * 8]);
            uint32_t b1 = __float_as_uint(bp[nt * 8 + 4 * PB_S]);
            mma_tf32(c[0][nt], a[0], b0, b1);
            mma_tf32(c[1][nt], a[1], b0, b1);
        }
    }
    __syncthreads();                       // done with sA/sB; reuse as stage

    float* stage = smem;                   // [64][196]
#pragma unroll
    for (int mt = 0; mt < 2; mt++) {
#pragma unroll
        for (int rs = 0; rs < 2; rs++) {
            int r = mbase + mt * 16 + grp + rs * 8;
            size_t off = (size_t)(rowbase + r) * Dc;
#pragma unroll
            for (int nt = 0; nt < 6; nt++) {
                int n = nbase + nt * 8 + tig * 2;
                float2 xv = *(const float2*)(x + off + n);
                float2 res;
                res.x = c[mt][nt][rs * 2 + 0] + bo[n]     + xv.x;
                res.y = c[mt][nt][rs * 2 + 1] + bo[n + 1] + xv.y;
                *(float2*)(g_y1 + off + n) = res;
                *(float2*)(stage + r * PST_S + n) = res;
            }
        }
    }
    __syncthreads();

    // fused LN2: warp w handles rows w, w+8, ... -> g_xn (fp32)
    for (int r = w; r < 64; r += 8) {
        float vv[6]; float s = 0.f;
#pragma unroll
        for (int i = 0; i < 6; i++) { vv[i] = stage[r * PST_S + lane + 32*i]; s += vv[i]; }
#pragma unroll
        for (int o = 16; o; o >>= 1) s += __shfl_xor_sync(0xffffffffu, s, o);
        float mean = s * (1.f/192.f);
        float vs = 0.f;
#pragma unroll
        for (int i = 0; i < 6; i++) { float dd = vv[i] - mean; vs += dd*dd; }
#pragma unroll
        for (int o = 16; o; o >>= 1) vs += __shfl_xor_sync(0xffffffffu, vs, o);
        float inv = rsqrtf(vs * (1.f/192.f) + 1e-3f);
#pragma unroll
        for (int i = 0; i < 6; i++) {
            int cc = lane + 32*i;
            g_xn[(size_t)(rowbase + r) * Dc + cc] =
                (vv[i] - mean) * inv * ln_g[cc] + ln_b[cc];
        }
    }
}

// ---------------- conv1d as tf32 tensor-core GEMM ----------------
#define SA_STRIDE 196
#define SB_STRIDE 200
#define SA_FLOATS (66 * SA_STRIDE)
#define SB_FLOATS (32 * SB_STRIDE)
#define CONV_SMEM_BYTES ((SA_FLOATS + 2 * SB_FLOATS) * 4)

template<int MODE>
__global__ __launch_bounds__(256, 2)
void conv_mma_kernel(const float* __restrict__ W,
                     const float* __restrict__ bias,
                     float* __restrict__ out)
{
    extern __shared__ float smem[];
    float* sA = smem;                    // [66][196]
    float* sB = smem + SA_FLOATS;        // [2][32][200]

    const int tid  = threadIdx.x;
    const int w    = tid >> 5;
    const int lane = tid & 31;
    const int tig  = lane & 3;
    const int grp  = lane >> 2;
    const int l0   = blockIdx.x * 64;
    const int bb   = blockIdx.y;
    const float* srcb = ((MODE == 0) ? g_xn : g_h) + (size_t)bb * Lc * Dc;

    for (int idx = tid; idx < 66 * 48; idx += 256) {
        int r = idx / 48, c4 = (idx % 48) * 4;
        int l = l0 - 1 + r; l = l < 0 ? 0 : (l > Lc - 1 ? Lc - 1 : l);
        float4 v = *(const float4*)(srcb + (size_t)l * Dc + c4);
        *(float4*)(sA + r * SA_STRIDE + c4) = tf32x4(v);
    }

    const int mbase = (w & 1) * 32;
    const int nbase = (w >> 1) * 48;
    float c[2][6][4];
#pragma unroll
    for (int i = 0; i < 2; i++)
#pragma unroll
        for (int j = 0; j < 6; j++)
#pragma unroll
            for (int q = 0; q < 4; q++) c[i][j][q] = 0.f;

    auto loadW = [&](int kc, int bf) {
        float* dstb = sB + bf * SB_FLOATS;
#pragma unroll
        for (int it = 0; it < 6; it++) {
            int idx = tid + it * 256;
            int k = idx / 48, c4 = (idx % 48) * 4;
            float4 v = *(const float4*)(W + ((size_t)(kc * 32 + k)) * Dc + c4);
            *(float4*)(dstb + k * SB_STRIDE + c4) = tf32x4(v);
        }
    };

    loadW(0, 0);
    __syncthreads();

    int buf = 0;
    for (int kc = 0; kc < 18; kc++) {
        if (kc < 17) loadW(kc + 1, buf ^ 1);
        const int t  = kc / 6;
        const int cc = (kc % 6) * 32;
        const float* bBuf = sB + buf * SB_FLOATS;
#pragma unroll
        for (int ks = 0; ks < 4; ks++) {
            const int c0 = cc + ks * 8;
            uint32_t a[2][4];
#pragma unroll
            for (int mt = 0; mt < 2; mt++) {
                const float* ap = sA + (mbase + mt * 16 + grp + t) * SA_STRIDE + c0 + tig;
                a[mt][0] = __float_as_uint(ap[0]);
                a[mt][1] = __float_as_uint(ap[8 * SA_STRIDE]);
                a[mt][2] = __float_as_uint(ap[4]);
                a[mt][3] = __float_as_uint(ap[8 * SA_STRIDE + 4]);
            }
            const float* bp = bBuf + (ks * 8 + tig) * SB_STRIDE + nbase + grp;
#pragma unroll
            for (int nt = 0; nt < 6; nt++) {
                uint32_t b0 = __float_as_uint(bp[nt * 8]);
                uint32_t b1 = __float_as_uint(bp[nt * 8 + 4 * SB_STRIDE]);
                mma_tf32(c[0][nt], a[0], b0, b1);
                mma_tf32(c[1][nt], a[1], b0, b1);
            }
        }
        __syncthreads();
        buf ^= 1;
    }

    float* dst = (MODE == 0) ? g_h : out;
#pragma unroll
    for (int mt = 0; mt < 2; mt++) {
#pragma unroll
        for (int rs = 0; rs < 2; rs++) {
            int l = l0 + mbase + mt * 16 + grp + rs * 8;
            bool interior = (l >= 1) && (l <= Lc - 2);
            size_t rowoff = ((size_t)bb * Lc + l) * Dc;
#pragma unroll
            for (int nt = 0; nt < 6; nt++) {
                int n = nbase + nt * 8 + tig * 2;
                float v0 = c[mt][nt][rs * 2 + 0] + bias[n];
                float v1 = c[mt][nt][rs * 2 + 1] + bias[n + 1];
                float2 res;
                if (MODE == 0) {
                    res.x = interior ? fmaxf(v0, 0.f) : 0.f;
                    res.y = interior ? fmaxf(v1, 0.f) : 0.f;
                } else {
                    float2 y = *(const float2*)(g_y1 + rowoff + n);
                    res.x = y.x + (interior ? v0 : 0.f);
                    res.y = y.y + (interior ? v1 : 0.f);
                }
                *(float2*)(dst + rowoff + n) = res;
            }
        }
    }
}

// ---------------- launcher ----------------
extern "C" void kernel_launch(void* const* d_in, const int* in_sizes, int n_in,
                              void* d_out, int out_size)
{
    const float* x     = (const float*)d_in[0];
    const float* ln1_g = (const float*)d_in[1];
    const float* ln1_b = (const float*)d_in[2];
    const float* wq    = (const float*)d_in[3];
    const float* bq    = (const float*)d_in[4];
    const float* wk    = (const float*)d_in[5];
    const float* bk    = (const float*)d_in[6];
    const float* wv    = (const float*)d_in[7];
    const float* bv    = (const float*)d_in[8];
    const float* wo    = (const float*)d_in[9];
    const float* bo    = (const float*)d_in[10];
    const float* ln2_g = (const float*)d_in[11];
    const float* ln2_b = (const float*)d_in[12];
    const float* c1_w  = (const float*)d_in[13];
    const float* c1_b  = (const float*)d_in[14];
    const float* c2_w  = (const float*)d_in[15];
    const float* c2_b  = (const float*)d_in[16];
    float* outp = (float*)d_out;

    cudaFuncSetAttribute(conv_mma_kernel<0>,
                         cudaFuncAttributeMaxDynamicSharedMemorySize, CONV_SMEM_BYTES);
    cudaFuncSetAttribute(conv_mma_kernel<1>,
                         cudaFuncAttributeMaxDynamicSharedMemorySize, CONV_SMEM_BYTES);
    cudaFuncSetAttribute(qkv_mma_kernel,
                         cudaFuncAttributeMaxDynamicSharedMemorySize, QKV_SMEM_BYTES);
    cudaFuncSetAttribute(proj_mma_kernel,
                         cudaFuncAttributeMaxDynamicSharedMemorySize, PROJ_SMEM_BYTES);

    qkv_mma_kernel<<<(Bc*Lc)/64, 192, QKV_SMEM_BYTES>>>(x, ln1_g, ln1_b,
                                                        wq, bq, wk, bk, wv, bv);
    attn_kernel<<<dim3(Lc/128, Hc, Bc), 256>>>();
    proj_mma_kernel<<<(Bc*Lc)/64, 256, PROJ_SMEM_BYTES>>>(x, wo, bo, ln2_g, ln2_b);
    conv_mma_kernel<0><<<dim3(Lc/64, Bc), 256, CONV_SMEM_BYTES>>>(c1_w, c1_b, outp);
    conv_mma_kernel<1><<<dim3(Lc/64, Bc), 256, CONV_SMEM_BYTES>>>(c2_w, c2_b, outp);
}